// round 5
// baseline (speedup 1.0000x reference)
#include <cuda_runtime.h>
#include <cstdint>

#define N_NODES 100000
#define F_IN 128
#define F_H  256
#define BN_EPS 1e-5f
#define L2_EPS 1e-12f

// ---------------- scratch (device globals; referenced ONLY from device code) --
__device__ __align__(16) float g_agg1[(size_t)N_NODES * F_IN];  // 51.2 MB
__device__ __align__(16) float g_h1  [(size_t)N_NODES * F_H];   // 102.4 MB
__device__ __align__(16) float g_agg2[(size_t)N_NODES * F_H];   // 102.4 MB
__device__ int   g_cnt[N_NODES];
__device__ float g_inv[N_NODES];
__device__ int   g_is64;   // 1 if edge_index is int64, 0 if int32

// ---------------- edge-index dtype detection ----------------
// int64 edges (values < 2^31, non-negative): every odd int32 word is 0.
// int32 edges: odd words are random node ids; all-zero prob ~ (1e-5)^128.
__global__ void detect_kernel(const int* __restrict__ ei_raw) {
    __shared__ int any_nonzero;
    if (threadIdx.x == 0) any_nonzero = 0;
    __syncthreads();
    int w = ei_raw[threadIdx.x * 2 + 1];           // words 1,3,...,255
    if (w != 0) atomicOr(&any_nonzero, 1);
    __syncthreads();
    if (threadIdx.x == 0) g_is64 = any_nonzero ? 0 : 1;
}

__device__ __forceinline__ int edge_at(const void* ei, size_t i) {
    if (g_is64) return (int)((const long long*)ei)[i];
    return ((const int*)ei)[i];
}

// ---------------- zero scratch ----------------
__global__ void zero_kernel() {
    size_t tid = (size_t)blockIdx.x * blockDim.x + threadIdx.x;
    size_t nthr = (size_t)gridDim.x * blockDim.x;
    const size_t n1 = (size_t)N_NODES * F_IN / 4;
    const size_t n2 = (size_t)N_NODES * F_H  / 4;
    float4 z = make_float4(0.f, 0.f, 0.f, 0.f);
    float4* a1 = (float4*)g_agg1;
    float4* a2 = (float4*)g_agg2;
    for (size_t i = tid; i < n1; i += nthr) a1[i] = z;
    for (size_t i = tid; i < n2; i += nthr) a2[i] = z;
    for (size_t i = tid; i < N_NODES; i += nthr) g_cnt[i] = 0;
}

// ---------------- degree ----------------
__global__ void degree_kernel(const void* __restrict__ ei, int E) {
    int e = blockIdx.x * blockDim.x + threadIdx.x;
    if (e < E) {
        int d = edge_at(ei, (size_t)E + e);
        if (d >= 0 && d < N_NODES) atomicAdd(&g_cnt[d], 1);
    }
}

__global__ void invdeg_kernel(int n) {
    int i = blockIdx.x * blockDim.x + threadIdx.x;
    if (i < n) g_inv[i] = 1.0f / fmaxf((float)g_cnt[i], 1.0f);
}

// ---------------- scatter-add ----------------
// LAYER 1: feat = xext (arg, F=128), agg = g_agg1
// LAYER 2: feat = g_h1 (device),     agg = g_agg2   (F=256)
// one warp per edge; float4 gather, scalar float red-adds
template<int LAYER>
__global__ void scatter_kernel(const void* __restrict__ ei,
                               const float* __restrict__ xext, int E) {
    constexpr int F = (LAYER == 1) ? F_IN : F_H;
    const float* feat = (LAYER == 1) ? xext : (const float*)g_h1;
    float* agg        = (LAYER == 1) ? g_agg1 : g_agg2;

    int gw = (blockIdx.x * blockDim.x + threadIdx.x) >> 5;
    int lane = threadIdx.x & 31;
    if (gw >= E) return;
    int src = edge_at(ei, gw);
    int dst = edge_at(ei, (size_t)E + gw);
    if ((unsigned)src >= N_NODES || (unsigned)dst >= N_NODES) return;
    const float4* srow = (const float4*)(feat + (size_t)src * F);
    float* drow = agg + (size_t)dst * F;
    #pragma unroll
    for (int i = 0; i < F / 128; i++) {
        int c = lane + 32 * i;
        float4 v = srow[c];
        float* p = drow + c * 4;
        atomicAdd(p + 0, v.x);
        atomicAdd(p + 1, v.y);
        atomicAdd(p + 2, v.z);
        atomicAdd(p + 3, v.w);
    }
}

// ---------------- fused SAGE GEMM ----------------
// LAYER 1: A0=g_agg1 (K0=128), A1=xext (K1=128), out=g_h1, BN+ReLU epilogue
// LAYER 2: A0=g_agg2 (K0=256), A1=g_h1 (K1=256), out=outp (d_out), plain
// out[n, c] = epi( (A0[n,:]*g_inv[n]) @ B0 + A1[n,:] @ B1 + bias )
template<int LAYER>
__global__ void __launch_bounds__(256)
sage_gemm_kernel(const float* __restrict__ xext,
                 const float* __restrict__ B0, const float* __restrict__ B1,
                 const float* __restrict__ bias,
                 const float* __restrict__ gamma, const float* __restrict__ beta,
                 const float* __restrict__ mu,    const float* __restrict__ var,
                 float* __restrict__ outp, int n_rows)
{
    constexpr int K0 = (LAYER == 1) ? F_IN : F_H;
    constexpr int K1 = (LAYER == 1) ? F_IN : F_H;
    constexpr bool BN_RELU = (LAYER == 1);
    const float* A0 = (LAYER == 1) ? g_agg1 : g_agg2;
    const float* A1 = (LAYER == 1) ? xext   : (const float*)g_h1;
    float* out      = (LAYER == 1) ? g_h1   : outp;

    __shared__ float As[16][128];
    __shared__ float Bs[16][128];

    const int t    = threadIdx.x;
    const int row0 = blockIdx.x * 128;
    const int col0 = blockIdx.y * 128;
    const int ty   = t >> 4;   // 0..15
    const int tx   = t & 15;   // 0..15

    float acc[8][8];
    #pragma unroll
    for (int i = 0; i < 8; i++)
        #pragma unroll
        for (int j = 0; j < 8; j++) acc[i][j] = 0.0f;

    const int KT = K0 + K1;
    for (int kt = 0; kt < KT; kt += 16) {
        const bool fromA0  = (kt < K0);
        const float* A     = fromA0 ? A0 : A1;
        const float* B     = fromA0 ? B0 : B1;
        const int stride   = fromA0 ? K0 : K1;
        const int kc       = fromA0 ? kt : (kt - K0);

        // load A tile: 128 rows x 16 k (2 float4 per thread)
        #pragma unroll
        for (int l = 0; l < 2; l++) {
            int v  = t + l * 256;
            int r  = v >> 2;
            int kq = v & 3;
            int gr = row0 + r;
            float4 f = make_float4(0.f, 0.f, 0.f, 0.f);
            if (gr < n_rows) {
                f = *(const float4*)(A + (size_t)gr * stride + kc + kq * 4);
                if (fromA0) {
                    float s = g_inv[gr];
                    f.x *= s; f.y *= s; f.z *= s; f.w *= s;
                }
            }
            As[kq * 4 + 0][r] = f.x;
            As[kq * 4 + 1][r] = f.y;
            As[kq * 4 + 2][r] = f.z;
            As[kq * 4 + 3][r] = f.w;
        }
        // load B tile: 16 k x 128 cols
        #pragma unroll
        for (int l = 0; l < 2; l++) {
            int v  = t + l * 256;
            int kr = v >> 5;
            int cq = v & 31;
            float4 f = *(const float4*)(B + (size_t)(kc + kr) * F_H + col0 + cq * 4);
            *(float4*)&Bs[kr][cq * 4] = f;
        }
        __syncthreads();

        #pragma unroll
        for (int k = 0; k < 16; k++) {
            float ra[8], rb[8];
            *(float4*)&ra[0] = *(const float4*)&As[k][ty * 8];
            *(float4*)&ra[4] = *(const float4*)&As[k][ty * 8 + 4];
            *(float4*)&rb[0] = *(const float4*)&Bs[k][tx * 8];
            *(float4*)&rb[4] = *(const float4*)&Bs[k][tx * 8 + 4];
            #pragma unroll
            for (int i = 0; i < 8; i++)
                #pragma unroll
                for (int j = 0; j < 8; j++)
                    acc[i][j] = fmaf(ra[i], rb[j], acc[i][j]);
        }
        __syncthreads();
    }

    // epilogue
    float cb[8], cs[8], csh[8];
    #pragma unroll
    for (int j = 0; j < 8; j++) {
        int c = col0 + tx * 8 + j;
        cb[j] = bias[c];
        if (BN_RELU) {
            float s = gamma[c] * rsqrtf(var[c] + BN_EPS);
            cs[j]  = s;
            csh[j] = beta[c] - mu[c] * s;
        }
    }
    #pragma unroll
    for (int i = 0; i < 8; i++) {
        int gr = row0 + ty * 8 + i;
        if (gr >= n_rows) continue;
        float vals[8];
        #pragma unroll
        for (int j = 0; j < 8; j++) {
            float v = acc[i][j] + cb[j];
            if (BN_RELU) v = fmaxf(fmaf(v, cs[j], csh[j]), 0.0f);
            vals[j] = v;
        }
        float* orow = out + (size_t)gr * F_H + col0 + tx * 8;
        *(float4*)&orow[0] = *(float4*)&vals[0];
        *(float4*)&orow[4] = *(float4*)&vals[4];
    }
}

// ---------------- row L2 normalize ----------------
__global__ void l2norm_kernel(float* __restrict__ out, int n_rows) {
    int warp = (blockIdx.x * blockDim.x + threadIdx.x) >> 5;
    int lane = threadIdx.x & 31;
    if (warp >= n_rows) return;
    float4* row = (float4*)(out + (size_t)warp * F_H);
    float4 a = row[lane];
    float4 b = row[lane + 32];
    float ss = a.x * a.x + a.y * a.y + a.z * a.z + a.w * a.w
             + b.x * b.x + b.y * b.y + b.z * b.z + b.w * b.w;
    #pragma unroll
    for (int o = 16; o > 0; o >>= 1)
        ss += __shfl_xor_sync(0xFFFFFFFFu, ss, o);
    float inv = 1.0f / fmaxf(sqrtf(ss), L2_EPS);
    a.x *= inv; a.y *= inv; a.z *= inv; a.w *= inv;
    b.x *= inv; b.y *= inv; b.z *= inv; b.w *= inv;
    row[lane] = a;
    row[lane + 32] = b;
}

// ---------------- launch ----------------
extern "C" void kernel_launch(void* const* d_in, const int* in_sizes, int n_in,
                              void* d_out, int out_size) {
    const float* x      = (const float*)d_in[0];
    const void*  ei     = d_in[1];                 // int32 or int64, detected on device
    const float* W1_l   = (const float*)d_in[2];
    const float* b1_l   = (const float*)d_in[3];
    const float* W1_r   = (const float*)d_in[4];
    const float* gamma  = (const float*)d_in[5];
    const float* beta   = (const float*)d_in[6];
    const float* mu     = (const float*)d_in[7];
    const float* var    = (const float*)d_in[8];
    const float* W2_l   = (const float*)d_in[9];
    const float* b2_l   = (const float*)d_in[10];
    const float* W2_r   = (const float*)d_in[11];
    float* out = (float*)d_out;

    const int N = in_sizes[0] / F_IN;     // 100000
    const int E = in_sizes[1] / 2;        // 800000

    detect_kernel<<<1, 128>>>((const int*)ei);
    zero_kernel<<<2048, 256>>>();

    degree_kernel<<<(E + 255) / 256, 256>>>(ei, E);
    invdeg_kernel<<<(N + 255) / 256, 256>>>(N);

    // layer-1 neighbor sum: g_agg1 += x[src]
    {
        long long thr = (long long)E * 32;
        scatter_kernel<1><<<(unsigned)((thr + 255) / 256), 256>>>(ei, x, E);
    }

    // h1 = relu(BN(mean1 @ W1_l + b1 + x @ W1_r)) -> g_h1
    {
        dim3 grid((N + 127) / 128, F_H / 128);
        sage_gemm_kernel<1><<<grid, 256>>>(
            x, W1_l, W1_r, b1_l, gamma, beta, mu, var, nullptr, N);
    }

    // layer-2 neighbor sum: g_agg2 += h1[src]
    {
        long long thr = (long long)E * 32;
        scatter_kernel<2><<<(unsigned)((thr + 255) / 256), 256>>>(ei, nullptr, E);
    }

    // h2 = mean2 @ W2_l + b2 + h1 @ W2_r -> d_out
    {
        dim3 grid((N + 127) / 128, F_H / 128);
        sage_gemm_kernel<2><<<grid, 256>>>(
            nullptr, W2_l, W2_r, b2_l, nullptr, nullptr, nullptr, nullptr, out, N);
    }

    l2norm_kernel<<<(N + 7) / 8, 256>>>(out, N);
}

// round 7
// speedup vs baseline: 1.4143x; 1.4143x over previous
#include <cuda_runtime.h>
#include <cuda_bf16.h>
#include <cstdint>

#define N_NODES 100000
#define F_IN 128
#define F_H  256
#define BN_EPS 1e-5f
#define L2_EPS 1e-12f

// ---------------- scratch (device globals; referenced ONLY from device code) --
__device__ __align__(16) float g_agg1[(size_t)N_NODES * F_IN];
__device__ __align__(16) float g_h1  [(size_t)N_NODES * F_H];
__device__ __align__(16) float g_agg2[(size_t)N_NODES * F_H];
__device__ int   g_cnt[N_NODES];
__device__ float g_inv[N_NODES];
__device__ int   g_is64;

// weights transposed + split to bf16 hi/lo: B[n][k], n = out col (256), k = in
__device__ __align__(16) __nv_bfloat16 g_B1_hi[256 * 256];
__device__ __align__(16) __nv_bfloat16 g_B1_lo[256 * 256];
__device__ __align__(16) __nv_bfloat16 g_B2_hi[256 * 512];
__device__ __align__(16) __nv_bfloat16 g_B2_lo[256 * 512];

// ---------------- edge-index dtype detection ----------------
__global__ void detect_kernel(const int* __restrict__ ei_raw) {
    __shared__ int any_nonzero;
    if (threadIdx.x == 0) any_nonzero = 0;
    __syncthreads();
    int w = ei_raw[threadIdx.x * 2 + 1];
    if (w != 0) atomicOr(&any_nonzero, 1);
    __syncthreads();
    if (threadIdx.x == 0) g_is64 = any_nonzero ? 0 : 1;
}

__device__ __forceinline__ int edge_at(const void* ei, size_t i) {
    if (g_is64) return (int)((const long long*)ei)[i];
    return ((const int*)ei)[i];
}

// ---------------- zero scratch ----------------
__global__ void zero_kernel() {
    size_t tid = (size_t)blockIdx.x * blockDim.x + threadIdx.x;
    size_t nthr = (size_t)gridDim.x * blockDim.x;
    const size_t n1 = (size_t)N_NODES * F_IN / 4;
    const size_t n2 = (size_t)N_NODES * F_H  / 4;
    float4 z = make_float4(0.f, 0.f, 0.f, 0.f);
    float4* a1 = (float4*)g_agg1;
    float4* a2 = (float4*)g_agg2;
    for (size_t i = tid; i < n1; i += nthr) a1[i] = z;
    for (size_t i = tid; i < n2; i += nthr) a2[i] = z;
    for (size_t i = tid; i < N_NODES; i += nthr) g_cnt[i] = 0;
}

// ---------------- weight prep: transpose + bf16 hi/lo split ----------------
__global__ void prep_B_kernel(const float* __restrict__ W1_l, const float* __restrict__ W1_r,
                              const float* __restrict__ W2_l, const float* __restrict__ W2_r) {
    int tid = blockIdx.x * blockDim.x + threadIdx.x;
    int nthr = gridDim.x * blockDim.x;
    for (int i = tid; i < 256 * 256; i += nthr) {
        int n = i >> 8, k = i & 255;
        float w = (k < 128) ? W1_l[k * 256 + n] : W1_r[(k - 128) * 256 + n];
        __nv_bfloat16 h = __float2bfloat16(w);
        g_B1_hi[i] = h;
        g_B1_lo[i] = __float2bfloat16(w - __bfloat162float(h));
    }
    for (int i = tid; i < 256 * 512; i += nthr) {
        int n = i >> 9, k = i & 511;
        float w = (k < 256) ? W2_l[k * 256 + n] : W2_r[(k - 256) * 256 + n];
        __nv_bfloat16 h = __float2bfloat16(w);
        g_B2_hi[i] = h;
        g_B2_lo[i] = __float2bfloat16(w - __bfloat162float(h));
    }
}

// ---------------- degree ----------------
__global__ void degree_kernel(const void* __restrict__ ei, int E) {
    int e = blockIdx.x * blockDim.x + threadIdx.x;
    if (e < E) {
        int d = edge_at(ei, (size_t)E + e);
        if (d >= 0 && d < N_NODES) atomicAdd(&g_cnt[d], 1);
    }
}

__global__ void invdeg_kernel(int n) {
    int i = blockIdx.x * blockDim.x + threadIdx.x;
    if (i < n) g_inv[i] = 1.0f / fmaxf((float)g_cnt[i], 1.0f);
}

// ---------------- scatter-add ----------------
template<int LAYER>
__global__ void scatter_kernel(const void* __restrict__ ei,
                               const float* __restrict__ xext, int E) {
    constexpr int F = (LAYER == 1) ? F_IN : F_H;
    const float* feat = (LAYER == 1) ? xext : (const float*)g_h1;
    float* agg        = (LAYER == 1) ? g_agg1 : g_agg2;

    int gw = (blockIdx.x * blockDim.x + threadIdx.x) >> 5;
    int lane = threadIdx.x & 31;
    if (gw >= E) return;
    int src = edge_at(ei, gw);
    int dst = edge_at(ei, (size_t)E + gw);
    if ((unsigned)src >= N_NODES || (unsigned)dst >= N_NODES) return;
    const float4* srow = (const float4*)(feat + (size_t)src * F);
    float* drow = agg + (size_t)dst * F;
    #pragma unroll
    for (int i = 0; i < F / 128; i++) {
        int c = lane + 32 * i;
        float4 v = srow[c];
        float* p = drow + c * 4;
        atomicAdd(p + 0, v.x);
        atomicAdd(p + 1, v.y);
        atomicAdd(p + 2, v.z);
        atomicAdd(p + 3, v.w);
    }
}

// ================= warp-level bf16 MMA GEMM (sm_80+ baseline PTX) ============
__device__ __forceinline__ void mma16816(float* c, const uint32_t* a, const uint32_t* b) {
    asm volatile(
        "mma.sync.aligned.m16n8k16.row.col.f32.bf16.bf16.f32 "
        "{%0,%1,%2,%3}, {%4,%5,%6,%7}, {%8,%9}, {%0,%1,%2,%3};"
        : "+f"(c[0]), "+f"(c[1]), "+f"(c[2]), "+f"(c[3])
        : "r"(a[0]), "r"(a[1]), "r"(a[2]), "r"(a[3]), "r"(b[0]), "r"(b[1]));
}

__device__ __forceinline__ uint32_t pack_bf16(float x, float y) {
    __nv_bfloat16 hx = __float2bfloat16(x);
    __nv_bfloat16 hy = __float2bfloat16(y);
    return (uint32_t)__bfloat16_as_ushort(hx) | ((uint32_t)__bfloat16_as_ushort(hy) << 16);
}

// dynamic smem (u32 units): AH@0 (128x20), AL@2560, BH@5120 (256x20), BL@10240
// stride 20 u32 per row: conflict-free, 16B-aligned uint4 stores
#define SM_AH 0
#define SM_AL 2560
#define SM_BH 5120
#define SM_BL 10240
#define SMEM_MMA (15360 * 4)

// CTA: 128 rows x 256 cols. 8 warps = 4(m) x 2(n); warp tile 32x128.
template<int LAYER>
__global__ void __launch_bounds__(256, 1)
mma_gemm_kernel(const float* __restrict__ xext,
                const float* __restrict__ bias,
                const float* __restrict__ gamma, const float* __restrict__ beta,
                const float* __restrict__ mu,    const float* __restrict__ var,
                float* __restrict__ outp, int n_rows)
{
    constexpr int KTOT  = (LAYER == 1) ? 256 : 512;
    constexpr int F0    = KTOT / 2;       // width of each A part
    constexpr int NCH   = KTOT / 32;      // 32-wide K chunks
    constexpr int CHALF = F0 / 32;        // chunks from agg part
    const float* A0 = (LAYER == 1) ? g_agg1 : g_agg2;
    const float* A1 = (LAYER == 1) ? xext   : (const float*)g_h1;
    const __nv_bfloat16* Bhi = (LAYER == 1) ? g_B1_hi : g_B2_hi;
    const __nv_bfloat16* Blo = (LAYER == 1) ? g_B1_lo : g_B2_lo;
    float* out = (LAYER == 1) ? g_h1 : outp;

    extern __shared__ uint32_t smu[];
    uint32_t* AH = smu + SM_AH;
    uint32_t* AL = smu + SM_AL;
    uint32_t* BH = smu + SM_BH;
    uint32_t* BL = smu + SM_BL;
    __shared__ float s_scale[256], s_shift[256];

    const int t = threadIdx.x, wid = t >> 5, lane = t & 31;
    const int grp = lane >> 2, tig = lane & 3;
    const int wm = wid & 3, wn = wid >> 2;
    const int row0 = blockIdx.x * 128;

    // per-column epilogue constants
    {
        if (LAYER == 1) {
            float s = gamma[t] * rsqrtf(var[t] + BN_EPS);
            s_scale[t] = s;
            s_shift[t] = beta[t] + (bias[t] - mu[t]) * s;
        } else {
            s_scale[t] = 1.0f;
            s_shift[t] = bias[t];
        }
    }

    float acc[2][16][4];
    #pragma unroll
    for (int mt = 0; mt < 2; mt++)
        #pragma unroll
        for (int nt = 0; nt < 16; nt++)
            #pragma unroll
            for (int q = 0; q < 4; q++) acc[mt][nt][q] = 0.0f;

    for (int ch = 0; ch < NCH; ch++) {
        const bool isAgg = (ch < CHALF);
        const float* Ab = isAgg ? A0 : A1;
        const int cb = (isAgg ? ch : ch - CHALF) * 32;

        // ---- stage A chunk: 128 rows x 32 f32 -> bf16 hi/lo (1024 float4) ----
        #pragma unroll
        for (int l = 0; l < 4; l++) {
            int id = t + l * 256;
            int r = id >> 3, q = id & 7;
            int gr = row0 + r;
            float4 v = make_float4(0.f, 0.f, 0.f, 0.f);
            float s = 1.0f;
            if (gr < n_rows) {
                v = *((const float4*)(Ab + (size_t)gr * F0 + cb) + q);
                if (isAgg) s = g_inv[gr];
            }
            float a0 = v.x * s, a1 = v.y * s, a2 = v.z * s, a3 = v.w * s;
            uint32_t h0 = pack_bf16(a0, a1), h1 = pack_bf16(a2, a3);
            float r0 = a0 - __bfloat162float(__float2bfloat16(a0));
            float r1 = a1 - __bfloat162float(__float2bfloat16(a1));
            float r2 = a2 - __bfloat162float(__float2bfloat16(a2));
            float r3 = a3 - __bfloat162float(__float2bfloat16(a3));
            uint32_t l0 = pack_bf16(r0, r1), l1 = pack_bf16(r2, r3);
            int b = r * 20 + q * 2;
            AH[b] = h0; AH[b + 1] = h1;
            AL[b] = l0; AL[b + 1] = l1;
        }
        // ---- stage B chunk: 256 n x 32 k bf16 hi/lo (uint4 copies) ----
        #pragma unroll
        for (int l = 0; l < 4; l++) {
            int id = t + l * 256;
            int n = id >> 2, q = id & 3;
            const uint4* sh = (const uint4*)(Bhi + (size_t)n * KTOT + ch * 32) + q;
            const uint4* sl = (const uint4*)(Blo + (size_t)n * KTOT + ch * 32) + q;
            *(uint4*)&BH[n * 20 + q * 4] = *sh;
            *(uint4*)&BL[n * 20 + q * 4] = *sl;
        }
        __syncthreads();

        // ---- compute: 2 k16 steps, 3 split passes ----
        #pragma unroll
        for (int s16 = 0; s16 < 2; s16++) {
            const int pb = s16 * 8;
            uint32_t ah[2][4], al[2][4];
            #pragma unroll
            for (int mt = 0; mt < 2; mt++) {
                int r = wm * 32 + mt * 16 + grp;
                ah[mt][0] = AH[r * 20 + pb + tig];
                ah[mt][1] = AH[(r + 8) * 20 + pb + tig];
                ah[mt][2] = AH[r * 20 + pb + tig + 4];
                ah[mt][3] = AH[(r + 8) * 20 + pb + tig + 4];
                al[mt][0] = AL[r * 20 + pb + tig];
                al[mt][1] = AL[(r + 8) * 20 + pb + tig];
                al[mt][2] = AL[r * 20 + pb + tig + 4];
                al[mt][3] = AL[(r + 8) * 20 + pb + tig + 4];
            }
            #pragma unroll
            for (int nt = 0; nt < 16; nt++) {
                int n = wn * 128 + nt * 8 + grp;
                uint32_t bh[2], bl[2];
                bh[0] = BH[n * 20 + pb + tig];
                bh[1] = BH[n * 20 + pb + tig + 4];
                bl[0] = BL[n * 20 + pb + tig];
                bl[1] = BL[n * 20 + pb + tig + 4];
                #pragma unroll
                for (int mt = 0; mt < 2; mt++) {
                    mma16816(acc[mt][nt], ah[mt], bh);
                    mma16816(acc[mt][nt], ah[mt], bl);
                    mma16816(acc[mt][nt], al[mt], bh);
                }
            }
        }
        __syncthreads();
    }

    // ---- epilogue ----
    #pragma unroll
    for (int mt = 0; mt < 2; mt++) {
        int r_lo = row0 + wm * 32 + mt * 16 + grp;
        int r_hi = r_lo + 8;
        #pragma unroll
        for (int nt = 0; nt < 16; nt++) {
            int c = wn * 128 + nt * 8 + 2 * tig;
            float s0 = s_scale[c],  sh0 = s_shift[c];
            float s1 = s_scale[c+1], sh1 = s_shift[c+1];
            if (r_lo < n_rows) {
                float v0 = fmaf(acc[mt][nt][0], s0, sh0);
                float v1 = fmaf(acc[mt][nt][1], s1, sh1);
                if (LAYER == 1) { v0 = fmaxf(v0, 0.f); v1 = fmaxf(v1, 0.f); }
                float2* p = (float2*)(out + (size_t)r_lo * 256 + c);
                *p = make_float2(v0, v1);
            }
            if (r_hi < n_rows) {
                float v2 = fmaf(acc[mt][nt][2], s0, sh0);
                float v3 = fmaf(acc[mt][nt][3], s1, sh1);
                if (LAYER == 1) { v2 = fmaxf(v2, 0.f); v3 = fmaxf(v3, 0.f); }
                float2* p = (float2*)(out + (size_t)r_hi * 256 + c);
                *p = make_float2(v2, v3);
            }
        }
    }
}

// ---------------- row L2 normalize ----------------
__global__ void l2norm_kernel(float* __restrict__ out, int n_rows) {
    int warp = (blockIdx.x * blockDim.x + threadIdx.x) >> 5;
    int lane = threadIdx.x & 31;
    if (warp >= n_rows) return;
    float4* row = (float4*)(out + (size_t)warp * F_H);
    float4 a = row[lane];
    float4 b = row[lane + 32];
    float ss = a.x * a.x + a.y * a.y + a.z * a.z + a.w * a.w
             + b.x * b.x + b.y * b.y + b.z * b.z + b.w * b.w;
    #pragma unroll
    for (int o = 16; o > 0; o >>= 1)
        ss += __shfl_xor_sync(0xFFFFFFFFu, ss, o);
    float inv = 1.0f / fmaxf(sqrtf(ss), L2_EPS);
    a.x *= inv; a.y *= inv; a.z *= inv; a.w *= inv;
    b.x *= inv; b.y *= inv; b.z *= inv; b.w *= inv;
    row[lane] = a;
    row[lane + 32] = b;
}

// ---------------- launch ----------------
extern "C" void kernel_launch(void* const* d_in, const int* in_sizes, int n_in,
                              void* d_out, int out_size) {
    const float* x      = (const float*)d_in[0];
    const void*  ei     = d_in[1];
    const float* W1_l   = (const float*)d_in[2];
    const float* b1_l   = (const float*)d_in[3];
    const float* W1_r   = (const float*)d_in[4];
    const float* gamma  = (const float*)d_in[5];
    const float* beta   = (const float*)d_in[6];
    const float* mu     = (const float*)d_in[7];
    const float* var    = (const float*)d_in[8];
    const float* W2_l   = (const float*)d_in[9];
    const float* b2_l   = (const float*)d_in[10];
    const float* W2_r   = (const float*)d_in[11];
    float* out = (float*)d_out;

    const int N = in_sizes[0] / F_IN;     // 100000
    const int E = in_sizes[1] / 2;        // 800000

    cudaFuncSetAttribute(mma_gemm_kernel<1>, cudaFuncAttributeMaxDynamicSharedMemorySize, SMEM_MMA);
    cudaFuncSetAttribute(mma_gemm_kernel<2>, cudaFuncAttributeMaxDynamicSharedMemorySize, SMEM_MMA);

    detect_kernel<<<1, 128>>>((const int*)ei);
    zero_kernel<<<2048, 256>>>();
    prep_B_kernel<<<512, 256>>>(W1_l, W1_r, W2_l, W2_r);

    degree_kernel<<<(E + 255) / 256, 256>>>(ei, E);
    invdeg_kernel<<<(N + 255) / 256, 256>>>(N);

    // layer-1 neighbor sum: g_agg1 += x[src]
    {
        long long thr = (long long)E * 32;
        scatter_kernel<1><<<(unsigned)((thr + 255) / 256), 256>>>(ei, x, E);
    }

    // h1 = relu(BN(mean1 @ W1_l + b1 + x @ W1_r)) -> g_h1   (HMMA tensor core)
    {
        int tiles = (N + 127) / 128;
        mma_gemm_kernel<1><<<tiles, 256, SMEM_MMA>>>(x, b1_l, gamma, beta, mu, var, nullptr, N);
    }

    // layer-2 neighbor sum: g_agg2 += h1[src]
    {
        long long thr = (long long)E * 32;
        scatter_kernel<2><<<(unsigned)((thr + 255) / 256), 256>>>(ei, nullptr, E);
    }

    // h2 = mean2 @ W2_l + b2 + h1 @ W2_r -> d_out   (HMMA tensor core)
    {
        int tiles = (N + 127) / 128;
        mma_gemm_kernel<2><<<tiles, 256, SMEM_MMA>>>(nullptr, b2_l, nullptr, nullptr, nullptr, nullptr, out, N);
    }

    l2norm_kernel<<<(N + 7) / 8, 256>>>(out, N);
}

// round 8
// speedup vs baseline: 2.6036x; 1.8409x over previous
#include <cuda_runtime.h>
#include <cuda_bf16.h>
#include <cstdint>

#define N_NODES 100000
#define E_MAX   800000
#define F_IN 128
#define F_H  256
#define BN_EPS 1e-5f
#define L2_EPS 1e-12f

// ---------------- scratch (device globals; referenced ONLY from device code) --
__device__ __align__(16) float g_agg1[(size_t)N_NODES * F_IN];
__device__ __align__(16) float g_h1  [(size_t)N_NODES * F_H];
__device__ __align__(16) float g_agg2[(size_t)N_NODES * F_H];
__device__ int   g_cnt[N_NODES];
__device__ int   g_cur[N_NODES];
__device__ int   g_rowptr[N_NODES + 1];
__device__ int   g_bsum[128];
__device__ int   g_esrc[E_MAX];
__device__ float g_inv[N_NODES];
__device__ int   g_is64;

// weights transposed + split to bf16 hi/lo: B[n][k], n = out col (256), k = in
__device__ __align__(16) __nv_bfloat16 g_B1_hi[256 * 256];
__device__ __align__(16) __nv_bfloat16 g_B1_lo[256 * 256];
__device__ __align__(16) __nv_bfloat16 g_B2_hi[256 * 512];
__device__ __align__(16) __nv_bfloat16 g_B2_lo[256 * 512];

// ---------------- edge-index dtype detection ----------------
__global__ void detect_kernel(const int* __restrict__ ei_raw) {
    __shared__ int any_nonzero;
    if (threadIdx.x == 0) any_nonzero = 0;
    __syncthreads();
    int w = ei_raw[threadIdx.x * 2 + 1];
    if (w != 0) atomicOr(&any_nonzero, 1);
    __syncthreads();
    if (threadIdx.x == 0) g_is64 = any_nonzero ? 0 : 1;
}

__device__ __forceinline__ int edge_at(const void* ei, size_t i) {
    if (g_is64) return (int)((const long long*)ei)[i];
    return ((const int*)ei)[i];
}

// ---------------- zero counters (agg buffers no longer need zeroing) ---------
__global__ void zero_kernel() {
    int i = blockIdx.x * blockDim.x + threadIdx.x;
    if (i < N_NODES) { g_cnt[i] = 0; g_cur[i] = 0; }
}

// ---------------- weight prep: transpose + bf16 hi/lo split ----------------
__global__ void prep_B_kernel(const float* __restrict__ W1_l, const float* __restrict__ W1_r,
                              const float* __restrict__ W2_l, const float* __restrict__ W2_r) {
    int tid = blockIdx.x * blockDim.x + threadIdx.x;
    int nthr = gridDim.x * blockDim.x;
    for (int i = tid; i < 256 * 256; i += nthr) {
        int n = i >> 8, k = i & 255;
        float w = (k < 128) ? W1_l[k * 256 + n] : W1_r[(k - 128) * 256 + n];
        __nv_bfloat16 h = __float2bfloat16(w);
        g_B1_hi[i] = h;
        g_B1_lo[i] = __float2bfloat16(w - __bfloat162float(h));
    }
    for (int i = tid; i < 256 * 512; i += nthr) {
        int n = i >> 9, k = i & 511;
        float w = (k < 256) ? W2_l[k * 256 + n] : W2_r[(k - 256) * 256 + n];
        __nv_bfloat16 h = __float2bfloat16(w);
        g_B2_hi[i] = h;
        g_B2_lo[i] = __float2bfloat16(w - __bfloat162float(h));
    }
}

// ---------------- degree histogram ----------------
__global__ void degree_kernel(const void* __restrict__ ei, int E) {
    int e = blockIdx.x * blockDim.x + threadIdx.x;
    if (e < E) {
        int d = edge_at(ei, (size_t)E + e);
        if (d >= 0 && d < N_NODES) atomicAdd(&g_cnt[d], 1);
    }
}

__global__ void invdeg_kernel(int n) {
    int i = blockIdx.x * blockDim.x + threadIdx.x;
    if (i < n) g_inv[i] = 1.0f / fmaxf((float)g_cnt[i], 1.0f);
}

// ---------------- 3-phase exclusive scan of g_cnt -> g_rowptr ----------------
// phase 1: per-block (1024 elems) exclusive scan; block total -> g_bsum
__global__ void scan1_kernel(int n) {
    __shared__ int sh[1024];
    int i = blockIdx.x * 1024 + threadIdx.x;
    int v = (i < n) ? g_cnt[i] : 0;
    sh[threadIdx.x] = v;
    __syncthreads();
    // Hillis-Steele inclusive scan
    #pragma unroll
    for (int o = 1; o < 1024; o <<= 1) {
        int add = (threadIdx.x >= o) ? sh[threadIdx.x - o] : 0;
        __syncthreads();
        sh[threadIdx.x] += add;
        __syncthreads();
    }
    if (i < n) g_rowptr[i] = sh[threadIdx.x] - v;     // exclusive
    if (threadIdx.x == 1023) g_bsum[blockIdx.x] = sh[1023];
}

// phase 2: exclusive scan of block sums (<=128 blocks, single warp-ish loop)
__global__ void scan2_kernel(int nblocks) {
    if (threadIdx.x == 0) {
        int acc = 0;
        for (int b = 0; b < nblocks; b++) {
            int v = g_bsum[b];
            g_bsum[b] = acc;
            acc += v;
        }
    }
}

// phase 3: add block offsets; write rowptr[N]
__global__ void scan3_kernel(int n, int E) {
    int i = blockIdx.x * 1024 + threadIdx.x;
    if (i < n) g_rowptr[i] += g_bsum[blockIdx.x];
    if (i == 0) g_rowptr[n] = E;
}

// ---------------- CSR fill: bucket edges by dst ----------------
__global__ void fill_kernel(const void* __restrict__ ei, int E) {
    int e = blockIdx.x * blockDim.x + threadIdx.x;
    if (e >= E) return;
    int src = edge_at(ei, e);
    int dst = edge_at(ei, (size_t)E + e);
    if ((unsigned)src >= N_NODES || (unsigned)dst >= N_NODES) return;
    int pos = g_rowptr[dst] + atomicAdd(&g_cur[dst], 1);
    g_esrc[pos] = src;
}

// ---------------- gather aggregation (no atomics) ----------------
// one warp per node; F=128: 1 float4/lane, F=256: 2 float4/lane
template<int LAYER>
__global__ void gather_kernel(const float* __restrict__ xext, int n_nodes) {
    constexpr int F = (LAYER == 1) ? F_IN : F_H;
    const float* feat = (LAYER == 1) ? xext : (const float*)g_h1;
    float* agg        = (LAYER == 1) ? g_agg1 : g_agg2;

    int node = (blockIdx.x * blockDim.x + threadIdx.x) >> 5;
    int lane = threadIdx.x & 31;
    if (node >= n_nodes) return;
    int beg = g_rowptr[node], end = g_rowptr[node + 1];

    if (LAYER == 1) {
        float4 acc = make_float4(0.f, 0.f, 0.f, 0.f);
        for (int i = beg; i < end; i++) {
            int s = __ldg(&g_esrc[i]);
            float4 v = __ldg((const float4*)(feat + (size_t)s * F) + lane);
            acc.x += v.x; acc.y += v.y; acc.z += v.z; acc.w += v.w;
        }
        *((float4*)(agg + (size_t)node * F) + lane) = acc;
    } else {
        float4 a0 = make_float4(0.f, 0.f, 0.f, 0.f);
        float4 a1 = make_float4(0.f, 0.f, 0.f, 0.f);
        for (int i = beg; i < end; i++) {
            int s = __ldg(&g_esrc[i]);
            const float4* row = (const float4*)(feat + (size_t)s * F);
            float4 v0 = __ldg(row + lane);
            float4 v1 = __ldg(row + lane + 32);
            a0.x += v0.x; a0.y += v0.y; a0.z += v0.z; a0.w += v0.w;
            a1.x += v1.x; a1.y += v1.y; a1.z += v1.z; a1.w += v1.w;
        }
        float4* orow = (float4*)(agg + (size_t)node * F);
        orow[lane] = a0;
        orow[lane + 32] = a1;
    }
}

// ================= warp-level bf16 MMA GEMM (sm_80+ baseline PTX) ============
__device__ __forceinline__ void mma16816(float* c, const uint32_t* a, const uint32_t* b) {
    asm volatile(
        "mma.sync.aligned.m16n8k16.row.col.f32.bf16.bf16.f32 "
        "{%0,%1,%2,%3}, {%4,%5,%6,%7}, {%8,%9}, {%0,%1,%2,%3};"
        : "+f"(c[0]), "+f"(c[1]), "+f"(c[2]), "+f"(c[3])
        : "r"(a[0]), "r"(a[1]), "r"(a[2]), "r"(a[3]), "r"(b[0]), "r"(b[1]));
}

__device__ __forceinline__ uint32_t pack_bf16(float x, float y) {
    __nv_bfloat16 hx = __float2bfloat16(x);
    __nv_bfloat16 hy = __float2bfloat16(y);
    return (uint32_t)__bfloat16_as_ushort(hx) | ((uint32_t)__bfloat16_as_ushort(hy) << 16);
}

#define SM_AH 0
#define SM_AL 2560
#define SM_BH 5120
#define SM_BL 10240
#define SMEM_MMA (15360 * 4)

// CTA: 128 rows x 256 cols. 8 warps = 4(m) x 2(n); warp tile 32x128.
template<int LAYER>
__global__ void __launch_bounds__(256, 1)
mma_gemm_kernel(const float* __restrict__ xext,
                const float* __restrict__ bias,
                const float* __restrict__ gamma, const float* __restrict__ beta,
                const float* __restrict__ mu,    const float* __restrict__ var,
                float* __restrict__ outp, int n_rows)
{
    constexpr int KTOT  = (LAYER == 1) ? 256 : 512;
    constexpr int F0    = KTOT / 2;
    constexpr int NCH   = KTOT / 32;
    constexpr int CHALF = F0 / 32;
    const float* A0 = (LAYER == 1) ? g_agg1 : g_agg2;
    const float* A1 = (LAYER == 1) ? xext   : (const float*)g_h1;
    const __nv_bfloat16* Bhi = (LAYER == 1) ? g_B1_hi : g_B2_hi;
    const __nv_bfloat16* Blo = (LAYER == 1) ? g_B1_lo : g_B2_lo;
    float* out = (LAYER == 1) ? g_h1 : outp;

    extern __shared__ uint32_t smu[];
    uint32_t* AH = smu + SM_AH;
    uint32_t* AL = smu + SM_AL;
    uint32_t* BH = smu + SM_BH;
    uint32_t* BL = smu + SM_BL;
    __shared__ float s_scale[256], s_shift[256];

    const int t = threadIdx.x, wid = t >> 5, lane = t & 31;
    const int grp = lane >> 2, tig = lane & 3;
    const int wm = wid & 3, wn = wid >> 2;
    const int row0 = blockIdx.x * 128;

    {
        if (LAYER == 1) {
            float s = gamma[t] * rsqrtf(var[t] + BN_EPS);
            s_scale[t] = s;
            s_shift[t] = beta[t] + (bias[t] - mu[t]) * s;
        } else {
            s_scale[t] = 1.0f;
            s_shift[t] = bias[t];
        }
    }

    float acc[2][16][4];
    #pragma unroll
    for (int mt = 0; mt < 2; mt++)
        #pragma unroll
        for (int nt = 0; nt < 16; nt++)
            #pragma unroll
            for (int q = 0; q < 4; q++) acc[mt][nt][q] = 0.0f;

    for (int ch = 0; ch < NCH; ch++) {
        const bool isAgg = (ch < CHALF);
        const float* Ab = isAgg ? A0 : A1;
        const int cb = (isAgg ? ch : ch - CHALF) * 32;

        #pragma unroll
        for (int l = 0; l < 4; l++) {
            int id = t + l * 256;
            int r = id >> 3, q = id & 7;
            int gr = row0 + r;
            float4 v = make_float4(0.f, 0.f, 0.f, 0.f);
            float s = 1.0f;
            if (gr < n_rows) {
                v = *((const float4*)(Ab + (size_t)gr * F0 + cb) + q);
                if (isAgg) s = g_inv[gr];
            }
            float a0 = v.x * s, a1 = v.y * s, a2 = v.z * s, a3 = v.w * s;
            uint32_t h0 = pack_bf16(a0, a1), h1 = pack_bf16(a2, a3);
            float r0 = a0 - __bfloat162float(__float2bfloat16(a0));
            float r1 = a1 - __bfloat162float(__float2bfloat16(a1));
            float r2 = a2 - __bfloat162float(__float2bfloat16(a2));
            float r3 = a3 - __bfloat162float(__float2bfloat16(a3));
            uint32_t l0 = pack_bf16(r0, r1), l1 = pack_bf16(r2, r3);
            int b = r * 20 + q * 2;
            AH[b] = h0; AH[b + 1] = h1;
            AL[b] = l0; AL[b + 1] = l1;
        }
        #pragma unroll
        for (int l = 0; l < 4; l++) {
            int id = t + l * 256;
            int n = id >> 2, q = id & 3;
            const uint4* sh = (const uint4*)(Bhi + (size_t)n * KTOT + ch * 32) + q;
            const uint4* sl = (const uint4*)(Blo + (size_t)n * KTOT + ch * 32) + q;
            *(uint4*)&BH[n * 20 + q * 4] = *sh;
            *(uint4*)&BL[n * 20 + q * 4] = *sl;
        }
        __syncthreads();

        #pragma unroll
        for (int s16 = 0; s16 < 2; s16++) {
            const int pb = s16 * 8;
            uint32_t ah[2][4], al[2][4];
            #pragma unroll
            for (int mt = 0; mt < 2; mt++) {
                int r = wm * 32 + mt * 16 + grp;
                ah[mt][0] = AH[r * 20 + pb + tig];
                ah[mt][1] = AH[(r + 8) * 20 + pb + tig];
                ah[mt][2] = AH[r * 20 + pb + tig + 4];
                ah[mt][3] = AH[(r + 8) * 20 + pb + tig + 4];
                al[mt][0] = AL[r * 20 + pb + tig];
                al[mt][1] = AL[(r + 8) * 20 + pb + tig];
                al[mt][2] = AL[r * 20 + pb + tig + 4];
                al[mt][3] = AL[(r + 8) * 20 + pb + tig + 4];
            }
            #pragma unroll
            for (int nt = 0; nt < 16; nt++) {
                int n = wn * 128 + nt * 8 + grp;
                uint32_t bh[2], bl[2];
                bh[0] = BH[n * 20 + pb + tig];
                bh[1] = BH[n * 20 + pb + tig + 4];
                bl[0] = BL[n * 20 + pb + tig];
                bl[1] = BL[n * 20 + pb + tig + 4];
                #pragma unroll
                for (int mt = 0; mt < 2; mt++) {
                    mma16816(acc[mt][nt], ah[mt], bh);
                    mma16816(acc[mt][nt], ah[mt], bl);
                    mma16816(acc[mt][nt], al[mt], bh);
                }
            }
        }
        __syncthreads();
    }

    #pragma unroll
    for (int mt = 0; mt < 2; mt++) {
        int r_lo = row0 + wm * 32 + mt * 16 + grp;
        int r_hi = r_lo + 8;
        #pragma unroll
        for (int nt = 0; nt < 16; nt++) {
            int c = wn * 128 + nt * 8 + 2 * tig;
            float s0 = s_scale[c],  sh0 = s_shift[c];
            float s1 = s_scale[c+1], sh1 = s_shift[c+1];
            if (r_lo < n_rows) {
                float v0 = fmaf(acc[mt][nt][0], s0, sh0);
                float v1 = fmaf(acc[mt][nt][1], s1, sh1);
                if (LAYER == 1) { v0 = fmaxf(v0, 0.f); v1 = fmaxf(v1, 0.f); }
                float2* p = (float2*)(out + (size_t)r_lo * 256 + c);
                *p = make_float2(v0, v1);
            }
            if (r_hi < n_rows) {
                float v2 = fmaf(acc[mt][nt][2], s0, sh0);
                float v3 = fmaf(acc[mt][nt][3], s1, sh1);
                if (LAYER == 1) { v2 = fmaxf(v2, 0.f); v3 = fmaxf(v3, 0.f); }
                float2* p = (float2*)(out + (size_t)r_hi * 256 + c);
                *p = make_float2(v2, v3);
            }
        }
    }
}

// ---------------- row L2 normalize ----------------
__global__ void l2norm_kernel(float* __restrict__ out, int n_rows) {
    int warp = (blockIdx.x * blockDim.x + threadIdx.x) >> 5;
    int lane = threadIdx.x & 31;
    if (warp >= n_rows) return;
    float4* row = (float4*)(out + (size_t)warp * F_H);
    float4 a = row[lane];
    float4 b = row[lane + 32];
    float ss = a.x * a.x + a.y * a.y + a.z * a.z + a.w * a.w
             + b.x * b.x + b.y * b.y + b.z * b.z + b.w * b.w;
    #pragma unroll
    for (int o = 16; o > 0; o >>= 1)
        ss += __shfl_xor_sync(0xFFFFFFFFu, ss, o);
    float inv = 1.0f / fmaxf(sqrtf(ss), L2_EPS);
    a.x *= inv; a.y *= inv; a.z *= inv; a.w *= inv;
    b.x *= inv; b.y *= inv; b.z *= inv; b.w *= inv;
    row[lane] = a;
    row[lane + 32] = b;
}

// ---------------- launch ----------------
extern "C" void kernel_launch(void* const* d_in, const int* in_sizes, int n_in,
                              void* d_out, int out_size) {
    const float* x      = (const float*)d_in[0];
    const void*  ei     = d_in[1];
    const float* W1_l   = (const float*)d_in[2];
    const float* b1_l   = (const float*)d_in[3];
    const float* W1_r   = (const float*)d_in[4];
    const float* gamma  = (const float*)d_in[5];
    const float* beta   = (const float*)d_in[6];
    const float* mu     = (const float*)d_in[7];
    const float* var    = (const float*)d_in[8];
    const float* W2_l   = (const float*)d_in[9];
    const float* b2_l   = (const float*)d_in[10];
    const float* W2_r   = (const float*)d_in[11];
    float* out = (float*)d_out;

    const int N = in_sizes[0] / F_IN;     // 100000
    const int E = in_sizes[1] / 2;        // 800000
    const int nsb = (N + 1023) / 1024;    // scan blocks (98)

    cudaFuncSetAttribute(mma_gemm_kernel<1>, cudaFuncAttributeMaxDynamicSharedMemorySize, SMEM_MMA);
    cudaFuncSetAttribute(mma_gemm_kernel<2>, cudaFuncAttributeMaxDynamicSharedMemorySize, SMEM_MMA);

    detect_kernel<<<1, 128>>>((const int*)ei);
    zero_kernel<<<(N + 255) / 256, 256>>>();
    prep_B_kernel<<<512, 256>>>(W1_l, W1_r, W2_l, W2_r);

    // CSR build
    degree_kernel<<<(E + 255) / 256, 256>>>(ei, E);
    invdeg_kernel<<<(N + 255) / 256, 256>>>(N);
    scan1_kernel<<<nsb, 1024>>>(N);
    scan2_kernel<<<1, 32>>>(nsb);
    scan3_kernel<<<nsb, 1024>>>(N, E);
    fill_kernel<<<(E + 255) / 256, 256>>>(ei, E);

    // layer-1 neighbor sum (gather): g_agg1[n] = sum x[src]
    gather_kernel<1><<<(N * 32 + 255) / 256, 256>>>(x, N);

    // h1 = relu(BN(mean1 @ W1_l + b1 + x @ W1_r)) -> g_h1
    {
        int tiles = (N + 127) / 128;
        mma_gemm_kernel<1><<<tiles, 256, SMEM_MMA>>>(x, b1_l, gamma, beta, mu, var, nullptr, N);
    }

    // layer-2 neighbor sum (gather): g_agg2[n] = sum h1[src]
    gather_kernel<2><<<(N * 32 + 255) / 256, 256>>>(nullptr, N);

    // h2 = mean2 @ W2_l + b2 + h1 @ W2_r -> d_out
    {
        int tiles = (N + 127) / 128;
        mma_gemm_kernel<2><<<tiles, 256, SMEM_MMA>>>(nullptr, b2_l, nullptr, nullptr, nullptr, nullptr, out, N);
    }

    l2norm_kernel<<<(N + 7) / 8, 256>>>(out, N);
}

// round 9
// speedup vs baseline: 2.8157x; 1.0814x over previous
#include <cuda_runtime.h>
#include <cuda_bf16.h>
#include <cstdint>

#define N_NODES 100000
#define E_MAX   800000
#define F_IN 128
#define F_H  256
#define BN_EPS 1e-5f
#define L2_EPS 1e-12f

// ---------------- scratch (device globals; referenced ONLY from device code) --
__device__ __align__(16) float g_h1[(size_t)N_NODES * F_H];          // 102.4 MB
// packed bf16 A matrices (u32 = 2 bf16). A1: [N][256] (agg128|self128),
// A2: [N][512] (agg256|self256). hi/lo split pair each.
__device__ __align__(16) uint32_t g_A1hi[(size_t)N_NODES * 128];
__device__ __align__(16) uint32_t g_A1lo[(size_t)N_NODES * 128];
__device__ __align__(16) uint32_t g_A2hi[(size_t)N_NODES * 256];
__device__ __align__(16) uint32_t g_A2lo[(size_t)N_NODES * 256];
__device__ int   g_cnt[N_NODES];
__device__ int   g_cur[N_NODES];
__device__ int   g_rowptr[N_NODES + 1];
__device__ int   g_bsum[128];
__device__ int   g_esrc[E_MAX];
__device__ int   g_is64;

// weights transposed + split to bf16 hi/lo: B[n][k], n = out col (256), k = in
__device__ __align__(16) __nv_bfloat16 g_B1_hi[256 * 256];
__device__ __align__(16) __nv_bfloat16 g_B1_lo[256 * 256];
__device__ __align__(16) __nv_bfloat16 g_B2_hi[256 * 512];
__device__ __align__(16) __nv_bfloat16 g_B2_lo[256 * 512];

// ---------------- helpers ----------------
__device__ __forceinline__ uint32_t pack_bf16(float x, float y) {
    __nv_bfloat16 hx = __float2bfloat16(x);
    __nv_bfloat16 hy = __float2bfloat16(y);
    return (uint32_t)__bfloat16_as_ushort(hx) | ((uint32_t)__bfloat16_as_ushort(hy) << 16);
}
__device__ __forceinline__ float bf16_round(float x) {
    return __bfloat162float(__float2bfloat16(x));
}

// ---------------- edge-index dtype detection ----------------
__global__ void detect_kernel(const int* __restrict__ ei_raw) {
    __shared__ int any_nonzero;
    if (threadIdx.x == 0) any_nonzero = 0;
    __syncthreads();
    int w = ei_raw[threadIdx.x * 2 + 1];
    if (w != 0) atomicOr(&any_nonzero, 1);
    __syncthreads();
    if (threadIdx.x == 0) g_is64 = any_nonzero ? 0 : 1;
}

__device__ __forceinline__ int edge_at(const void* ei, size_t i) {
    if (g_is64) return (int)((const long long*)ei)[i];
    return ((const int*)ei)[i];
}

// ---------------- zero counters ----------------
__global__ void zero_kernel() {
    int i = blockIdx.x * blockDim.x + threadIdx.x;
    if (i < N_NODES) { g_cnt[i] = 0; g_cur[i] = 0; }
}

// ---------------- weight prep: transpose + bf16 hi/lo split ----------------
__global__ void prep_B_kernel(const float* __restrict__ W1_l, const float* __restrict__ W1_r,
                              const float* __restrict__ W2_l, const float* __restrict__ W2_r) {
    int tid = blockIdx.x * blockDim.x + threadIdx.x;
    int nthr = gridDim.x * blockDim.x;
    for (int i = tid; i < 256 * 256; i += nthr) {
        int n = i >> 8, k = i & 255;
        float w = (k < 128) ? W1_l[k * 256 + n] : W1_r[(k - 128) * 256 + n];
        __nv_bfloat16 h = __float2bfloat16(w);
        g_B1_hi[i] = h;
        g_B1_lo[i] = __float2bfloat16(w - __bfloat162float(h));
    }
    for (int i = tid; i < 256 * 512; i += nthr) {
        int n = i >> 9, k = i & 511;
        float w = (k < 256) ? W2_l[k * 256 + n] : W2_r[(k - 256) * 256 + n];
        __nv_bfloat16 h = __float2bfloat16(w);
        g_B2_hi[i] = h;
        g_B2_lo[i] = __float2bfloat16(w - __bfloat162float(h));
    }
}

// ---------------- degree histogram ----------------
__global__ void degree_kernel(const void* __restrict__ ei, int E) {
    int e = blockIdx.x * blockDim.x + threadIdx.x;
    if (e < E) {
        int d = edge_at(ei, (size_t)E + e);
        if (d >= 0 && d < N_NODES) atomicAdd(&g_cnt[d], 1);
    }
}

// ---------------- 3-phase exclusive scan of g_cnt -> g_rowptr ----------------
__global__ void scan1_kernel(int n) {
    __shared__ int sh[1024];
    int i = blockIdx.x * 1024 + threadIdx.x;
    int v = (i < n) ? g_cnt[i] : 0;
    sh[threadIdx.x] = v;
    __syncthreads();
    #pragma unroll
    for (int o = 1; o < 1024; o <<= 1) {
        int add = (threadIdx.x >= o) ? sh[threadIdx.x - o] : 0;
        __syncthreads();
        sh[threadIdx.x] += add;
        __syncthreads();
    }
    if (i < n) g_rowptr[i] = sh[threadIdx.x] - v;
    if (threadIdx.x == 1023) g_bsum[blockIdx.x] = sh[1023];
}

__global__ void scan2_kernel(int nblocks) {
    if (threadIdx.x == 0) {
        int acc = 0;
        for (int b = 0; b < nblocks; b++) {
            int v = g_bsum[b];
            g_bsum[b] = acc;
            acc += v;
        }
    }
}

__global__ void scan3_kernel(int n, int E) {
    int i = blockIdx.x * 1024 + threadIdx.x;
    if (i < n) g_rowptr[i] += g_bsum[blockIdx.x];
    if (i == 0) g_rowptr[n] = E;
}

// ---------------- CSR fill ----------------
__global__ void fill_kernel(const void* __restrict__ ei, int E) {
    int e = blockIdx.x * blockDim.x + threadIdx.x;
    if (e >= E) return;
    int src = edge_at(ei, e);
    int dst = edge_at(ei, (size_t)E + e);
    if ((unsigned)src >= N_NODES || (unsigned)dst >= N_NODES) return;
    int pos = g_rowptr[dst] + atomicAdd(&g_cur[dst], 1);
    g_esrc[pos] = src;
}

// ---------------- gather aggregation -> packed bf16 hi/lo ----------------
// one warp per node; applies mean (1/deg) and writes hi/lo into A matrix cols [0, F)
template<int LAYER>
__global__ void gather_kernel(const float* __restrict__ xext, int n_nodes) {
    constexpr int F = (LAYER == 1) ? F_IN : F_H;
    constexpr int RSTRIDE = (LAYER == 1) ? 128 : 256;     // u32 per A row
    const float* feat = (LAYER == 1) ? xext : (const float*)g_h1;
    uint32_t* Ahi = (LAYER == 1) ? g_A1hi : g_A2hi;
    uint32_t* Alo = (LAYER == 1) ? g_A1lo : g_A2lo;

    int node = (blockIdx.x * blockDim.x + threadIdx.x) >> 5;
    int lane = threadIdx.x & 31;
    if (node >= n_nodes) return;
    int beg = g_rowptr[node], end = g_rowptr[node + 1];
    float inv = 1.0f / fmaxf((float)(end - beg), 1.0f);

    if (LAYER == 1) {
        float4 acc = make_float4(0.f, 0.f, 0.f, 0.f);
        for (int i = beg; i < end; i++) {
            int s = __ldg(&g_esrc[i]);
            float4 v = __ldg((const float4*)(feat + (size_t)s * F) + lane);
            acc.x += v.x; acc.y += v.y; acc.z += v.z; acc.w += v.w;
        }
        float a0 = acc.x * inv, a1 = acc.y * inv, a2 = acc.z * inv, a3 = acc.w * inv;
        size_t idx = (size_t)node * RSTRIDE + lane * 2;
        Ahi[idx]     = pack_bf16(a0, a1);
        Ahi[idx + 1] = pack_bf16(a2, a3);
        Alo[idx]     = pack_bf16(a0 - bf16_round(a0), a1 - bf16_round(a1));
        Alo[idx + 1] = pack_bf16(a2 - bf16_round(a2), a3 - bf16_round(a3));
    } else {
        float4 s0 = make_float4(0.f, 0.f, 0.f, 0.f);
        float4 s1 = make_float4(0.f, 0.f, 0.f, 0.f);
        for (int i = beg; i < end; i++) {
            int s = __ldg(&g_esrc[i]);
            const float4* row = (const float4*)(feat + (size_t)s * F);
            float4 v0 = __ldg(row + lane);
            float4 v1 = __ldg(row + lane + 32);
            s0.x += v0.x; s0.y += v0.y; s0.z += v0.z; s0.w += v0.w;
            s1.x += v1.x; s1.y += v1.y; s1.z += v1.z; s1.w += v1.w;
        }
        float b0 = s0.x * inv, b1 = s0.y * inv, b2 = s0.z * inv, b3 = s0.w * inv;
        float c0 = s1.x * inv, c1 = s1.y * inv, c2 = s1.z * inv, c3 = s1.w * inv;
        size_t i0 = (size_t)node * RSTRIDE + lane * 2;
        size_t i1 = i0 + 64;
        Ahi[i0]     = pack_bf16(b0, b1);
        Ahi[i0 + 1] = pack_bf16(b2, b3);
        Ahi[i1]     = pack_bf16(c0, c1);
        Ahi[i1 + 1] = pack_bf16(c2, c3);
        Alo[i0]     = pack_bf16(b0 - bf16_round(b0), b1 - bf16_round(b1));
        Alo[i0 + 1] = pack_bf16(b2 - bf16_round(b2), b3 - bf16_round(b3));
        Alo[i1]     = pack_bf16(c0 - bf16_round(c0), c1 - bf16_round(c1));
        Alo[i1 + 1] = pack_bf16(c2 - bf16_round(c2), c3 - bf16_round(c3));
    }
}

// ---------------- convert x into A1 self half (cols 128..255) ----------------
__global__ void convert_x_kernel(const float* __restrict__ x, int n_nodes) {
    int i = blockIdx.x * blockDim.x + threadIdx.x;   // one float4 each
    int total = n_nodes * 32;
    if (i >= total) return;
    int node = i >> 5, q = i & 31;
    float4 v = __ldg((const float4*)(x + (size_t)node * 128) + q);
    size_t idx = (size_t)node * 128 + 64 + q * 2;
    g_A1hi[idx]     = pack_bf16(v.x, v.y);
    g_A1hi[idx + 1] = pack_bf16(v.z, v.w);
    g_A1lo[idx]     = pack_bf16(v.x - bf16_round(v.x), v.y - bf16_round(v.y));
    g_A1lo[idx + 1] = pack_bf16(v.z - bf16_round(v.z), v.w - bf16_round(v.w));
}

// ================= warp-level bf16 MMA GEMM, cp.async double-buffered ========
__device__ __forceinline__ void mma16816(float* c, const uint32_t* a, const uint32_t* b) {
    asm volatile(
        "mma.sync.aligned.m16n8k16.row.col.f32.bf16.bf16.f32 "
        "{%0,%1,%2,%3}, {%4,%5,%6,%7}, {%8,%9}, {%0,%1,%2,%3};"
        : "+f"(c[0]), "+f"(c[1]), "+f"(c[2]), "+f"(c[3])
        : "r"(a[0]), "r"(a[1]), "r"(a[2]), "r"(a[3]), "r"(b[0]), "r"(b[1]));
}

__device__ __forceinline__ void cp16(uint32_t smem_byte, const void* gmem) {
    asm volatile("cp.async.cg.shared.global [%0], [%1], 16;" :: "r"(smem_byte), "l"(gmem));
}

// stage layout (u32 units): AH@0 (128x20), AL@2560, BH@5120 (256x20), BL@10240
#define SM_AH 0
#define SM_AL 2560
#define SM_BH 5120
#define SM_BL 10240
#define STG_U32 15360
#define SMEM_MMA (2 * STG_U32 * 4)      // 122880 B

// CTA: 128 rows x 256 cols. 8 warps = 4(m) x 2(n); warp tile 32x128.
template<int LAYER>
__global__ void __launch_bounds__(256, 1)
mma_gemm_kernel(const float* __restrict__ bias,
                const float* __restrict__ gamma, const float* __restrict__ beta,
                const float* __restrict__ mu,    const float* __restrict__ var,
                float* __restrict__ outp, int n_rows)
{
    constexpr int KTOT = (LAYER == 1) ? 256 : 512;
    constexpr int NCH  = KTOT / 32;
    constexpr int RS   = KTOT / 2;        // A row stride in u32
    const uint32_t* Ahi = (LAYER == 1) ? g_A1hi : g_A2hi;
    const uint32_t* Alo = (LAYER == 1) ? g_A1lo : g_A2lo;
    const __nv_bfloat16* Bhi = (LAYER == 1) ? g_B1_hi : g_B2_hi;
    const __nv_bfloat16* Blo = (LAYER == 1) ? g_B1_lo : g_B2_lo;
    float* out = (LAYER == 1) ? g_h1 : outp;

    extern __shared__ uint32_t smu[];
    __shared__ float s_scale[256], s_shift[256];

    const int t = threadIdx.x, wid = t >> 5, lane = t & 31;
    const int grp = lane >> 2, tig = lane & 3;
    const int wm = wid & 3, wn = wid >> 2;
    const int row0 = blockIdx.x * 128;

    uint32_t smem_base;
    asm("{ .reg .u64 tt; cvta.to.shared.u64 tt, %1; cvt.u32.u64 %0, tt; }"
        : "=r"(smem_base) : "l"(smu));

    if (LAYER == 1) {
        float s = gamma[t] * rsqrtf(var[t] + BN_EPS);
        s_scale[t] = s;
        s_shift[t] = beta[t] + (bias[t] - mu[t]) * s;
    } else {
        s_scale[t] = 1.0f;
        s_shift[t] = bias[t];
    }

    // chunk loader: A 128x32 bf16 (hi+lo), B 256x32 bf16 (hi+lo)
    auto load_chunk = [&](int ch, int stg) {
        uint32_t sb = smem_base + stg * (STG_U32 * 4);
        #pragma unroll
        for (int l = 0; l < 2; l++) {
            int id = t + l * 256;         // 0..511
            int r = id >> 2, q = id & 3;
            int gr = row0 + r;
            if (gr >= n_rows) gr = n_rows - 1;
            size_t off = ((size_t)gr * RS + ch * 16 + q * 4) * 4;   // bytes
            cp16(sb + (SM_AH + r * 20 + q * 4) * 4, (const char*)Ahi + off);
            cp16(sb + (SM_AL + r * 20 + q * 4) * 4, (const char*)Alo + off);
        }
        #pragma unroll
        for (int l = 0; l < 4; l++) {
            int id = t + l * 256;         // 0..1023
            int n = id >> 2, q = id & 3;
            size_t off = ((size_t)n * KTOT + ch * 32) * 2 + q * 16; // bytes
            cp16(sb + (SM_BH + n * 20 + q * 4) * 4, (const char*)Bhi + off);
            cp16(sb + (SM_BL + n * 20 + q * 4) * 4, (const char*)Blo + off);
        }
        asm volatile("cp.async.commit_group;");
    };

    float acc[2][16][4];
    #pragma unroll
    for (int mt = 0; mt < 2; mt++)
        #pragma unroll
        for (int nt = 0; nt < 16; nt++)
            #pragma unroll
            for (int q = 0; q < 4; q++) acc[mt][nt][q] = 0.0f;

    load_chunk(0, 0);

    for (int ch = 0; ch < NCH; ch++) {
        if (ch + 1 < NCH) {
            load_chunk(ch + 1, (ch + 1) & 1);
            asm volatile("cp.async.wait_group 1;");
        } else {
            asm volatile("cp.async.wait_group 0;");
        }
        __syncthreads();

        const uint32_t* AH = smu + (ch & 1) * STG_U32 + SM_AH;
        const uint32_t* AL = smu + (ch & 1) * STG_U32 + SM_AL;
        const uint32_t* BH = smu + (ch & 1) * STG_U32 + SM_BH;
        const uint32_t* BL = smu + (ch & 1) * STG_U32 + SM_BL;

        #pragma unroll
        for (int s16 = 0; s16 < 2; s16++) {
            const int pb = s16 * 8;
            uint32_t ah[2][4], al[2][4];
            #pragma unroll
            for (int mt = 0; mt < 2; mt++) {
                int r = wm * 32 + mt * 16 + grp;
                ah[mt][0] = AH[r * 20 + pb + tig];
                ah[mt][1] = AH[(r + 8) * 20 + pb + tig];
                ah[mt][2] = AH[r * 20 + pb + tig + 4];
                ah[mt][3] = AH[(r + 8) * 20 + pb + tig + 4];
                al[mt][0] = AL[r * 20 + pb + tig];
                al[mt][1] = AL[(r + 8) * 20 + pb + tig];
                al[mt][2] = AL[r * 20 + pb + tig + 4];
                al[mt][3] = AL[(r + 8) * 20 + pb + tig + 4];
            }
            #pragma unroll
            for (int nt = 0; nt < 16; nt++) {
                int n = wn * 128 + nt * 8 + grp;
                uint32_t bh[2], bl[2];
                bh[0] = BH[n * 20 + pb + tig];
                bh[1] = BH[n * 20 + pb + tig + 4];
                bl[0] = BL[n * 20 + pb + tig];
                bl[1] = BL[n * 20 + pb + tig + 4];
                #pragma unroll
                for (int mt = 0; mt < 2; mt++) {
                    mma16816(acc[mt][nt], ah[mt], bh);
                    mma16816(acc[mt][nt], ah[mt], bl);
                    mma16816(acc[mt][nt], al[mt], bh);
                }
            }
        }
        __syncthreads();
    }

    // ---- epilogue; LAYER 1 also emits A2 self half (cols 256..511) hi/lo ----
    #pragma unroll
    for (int mt = 0; mt < 2; mt++) {
        int r_lo = row0 + wm * 32 + mt * 16 + grp;
        int r_hi = r_lo + 8;
        #pragma unroll
        for (int nt = 0; nt < 16; nt++) {
            int c = wn * 128 + nt * 8 + 2 * tig;
            float s0 = s_scale[c],   sh0 = s_shift[c];
            float s1 = s_scale[c+1], sh1 = s_shift[c+1];
            if (r_lo < n_rows) {
                float v0 = fmaf(acc[mt][nt][0], s0, sh0);
                float v1 = fmaf(acc[mt][nt][1], s1, sh1);
                if (LAYER == 1) { v0 = fmaxf(v0, 0.f); v1 = fmaxf(v1, 0.f); }
                *(float2*)(out + (size_t)r_lo * 256 + c) = make_float2(v0, v1);
                if (LAYER == 1) {
                    size_t ai = (size_t)r_lo * 256 + 128 + (c >> 1);
                    g_A2hi[ai] = pack_bf16(v0, v1);
                    g_A2lo[ai] = pack_bf16(v0 - bf16_round(v0), v1 - bf16_round(v1));
                }
            }
            if (r_hi < n_rows) {
                float v2 = fmaf(acc[mt][nt][2], s0, sh0);
                float v3 = fmaf(acc[mt][nt][3], s1, sh1);
                if (LAYER == 1) { v2 = fmaxf(v2, 0.f); v3 = fmaxf(v3, 0.f); }
                *(float2*)(out + (size_t)r_hi * 256 + c) = make_float2(v2, v3);
                if (LAYER == 1) {
                    size_t ai = (size_t)r_hi * 256 + 128 + (c >> 1);
                    g_A2hi[ai] = pack_bf16(v2, v3);
                    g_A2lo[ai] = pack_bf16(v2 - bf16_round(v2), v3 - bf16_round(v3));
                }
            }
        }
    }
}

// ---------------- row L2 normalize ----------------
__global__ void l2norm_kernel(float* __restrict__ out, int n_rows) {
    int warp = (blockIdx.x * blockDim.x + threadIdx.x) >> 5;
    int lane = threadIdx.x & 31;
    if (warp >= n_rows) return;
    float4* row = (float4*)(out + (size_t)warp * F_H);
    float4 a = row[lane];
    float4 b = row[lane + 32];
    float ss = a.x * a.x + a.y * a.y + a.z * a.z + a.w * a.w
             + b.x * b.x + b.y * b.y + b.z * b.z + b.w * b.w;
    #pragma unroll
    for (int o = 16; o > 0; o >>= 1)
        ss += __shfl_xor_sync(0xFFFFFFFFu, ss, o);
    float inv = 1.0f / fmaxf(sqrtf(ss), L2_EPS);
    a.x *= inv; a.y *= inv; a.z *= inv; a.w *= inv;
    b.x *= inv; b.y *= inv; b.z *= inv; b.w *= inv;
    row[lane] = a;
    row[lane + 32] = b;
}

// ---------------- launch ----------------
extern "C" void kernel_launch(void* const* d_in, const int* in_sizes, int n_in,
                              void* d_out, int out_size) {
    const float* x      = (const float*)d_in[0];
    const void*  ei     = d_in[1];
    const float* W1_l   = (const float*)d_in[2];
    const float* b1_l   = (const float*)d_in[3];
    const float* W1_r   = (const float*)d_in[4];
    const float* gamma  = (const float*)d_in[5];
    const float* beta   = (const float*)d_in[6];
    const float* mu     = (const float*)d_in[7];
    const float* var    = (const float*)d_in[8];
    const float* W2_l   = (const float*)d_in[9];
    const float* b2_l   = (const float*)d_in[10];
    const float* W2_r   = (const float*)d_in[11];
    float* out = (float*)d_out;

    const int N = in_sizes[0] / F_IN;     // 100000
    const int E = in_sizes[1] / 2;        // 800000
    const int nsb = (N + 1023) / 1024;

    cudaFuncSetAttribute(mma_gemm_kernel<1>, cudaFuncAttributeMaxDynamicSharedMemorySize, SMEM_MMA);
    cudaFuncSetAttribute(mma_gemm_kernel<2>, cudaFuncAttributeMaxDynamicSharedMemorySize, SMEM_MMA);

    detect_kernel<<<1, 128>>>((const int*)ei);
    zero_kernel<<<(N + 255) / 256, 256>>>();
    prep_B_kernel<<<512, 256>>>(W1_l, W1_r, W2_l, W2_r);

    // CSR build
    degree_kernel<<<(E + 255) / 256, 256>>>(ei, E);
    scan1_kernel<<<nsb, 1024>>>(N);
    scan2_kernel<<<1, 32>>>(nsb);
    scan3_kernel<<<nsb, 1024>>>(N, E);
    fill_kernel<<<(E + 255) / 256, 256>>>(ei, E);

    // layer-1: A1 = [mean(x nbrs) | x]  (bf16 hi/lo packed)
    gather_kernel<1><<<(N * 32 + 255) / 256, 256>>>(x, N);
    convert_x_kernel<<<(N * 32 + 255) / 256, 256>>>(x, N);

    // h1 = relu(BN(A1 @ B1)) -> g_h1 (+ A2 self half)
    {
        int tiles = (N + 127) / 128;
        mma_gemm_kernel<1><<<tiles, 256, SMEM_MMA>>>(b1_l, gamma, beta, mu, var, nullptr, N);
    }

    // layer-2: A2[:, 0:256] = mean(h1 nbrs)
    gather_kernel<2><<<(N * 32 + 255) / 256, 256>>>(nullptr, N);

    // out = A2 @ B2 + b2
    {
        int tiles = (N + 127) / 128;
        mma_gemm_kernel<2><<<tiles, 256, SMEM_MMA>>>(b2_l, nullptr, nullptr, nullptr, nullptr, out, N);
    }

    l2norm_kernel<<<(N + 7) / 8, 256>>>(out, N);
}

// round 10
// speedup vs baseline: 2.9022x; 1.0307x over previous
#include <cuda_runtime.h>
#include <cuda_bf16.h>
#include <cstdint>

#define N_NODES 100000
#define E_MAX   800000
#define F_IN 128
#define F_H  256
#define BN_EPS 1e-5f
#define L2_EPS 1e-12f

// ---------------- scratch (device globals; referenced ONLY from device code) --
__device__ __align__(16) float g_h1[(size_t)N_NODES * F_H];
__device__ __align__(16) uint32_t g_A1hi[(size_t)N_NODES * 128];
__device__ __align__(16) uint32_t g_A1lo[(size_t)N_NODES * 128];
__device__ __align__(16) uint32_t g_A2hi[(size_t)N_NODES * 256];
__device__ __align__(16) uint32_t g_A2lo[(size_t)N_NODES * 256];
__device__ int   g_cnt[N_NODES];
__device__ int   g_cur[N_NODES];
__device__ int   g_rowptr[N_NODES + 1];
__device__ int   g_bsum[128];
__device__ int   g_esrc[E_MAX];
__device__ int   g_is64;

__device__ __align__(16) __nv_bfloat16 g_B1_hi[256 * 256];
__device__ __align__(16) __nv_bfloat16 g_B1_lo[256 * 256];
__device__ __align__(16) __nv_bfloat16 g_B2_hi[256 * 512];
__device__ __align__(16) __nv_bfloat16 g_B2_lo[256 * 512];

// ---------------- helpers ----------------
__device__ __forceinline__ uint32_t pack_bf16(float x, float y) {
    __nv_bfloat16 hx = __float2bfloat16(x);
    __nv_bfloat16 hy = __float2bfloat16(y);
    return (uint32_t)__bfloat16_as_ushort(hx) | ((uint32_t)__bfloat16_as_ushort(hy) << 16);
}
__device__ __forceinline__ float bf16_round(float x) {
    return __bfloat162float(__float2bfloat16(x));
}

// ---------------- edge-index dtype detection ----------------
__global__ void detect_kernel(const int* __restrict__ ei_raw) {
    __shared__ int any_nonzero;
    if (threadIdx.x == 0) any_nonzero = 0;
    __syncthreads();
    int w = ei_raw[threadIdx.x * 2 + 1];
    if (w != 0) atomicOr(&any_nonzero, 1);
    __syncthreads();
    if (threadIdx.x == 0) g_is64 = any_nonzero ? 0 : 1;
}

__device__ __forceinline__ int edge_at(const void* ei, size_t i) {
    if (g_is64) return (int)((const long long*)ei)[i];
    return ((const int*)ei)[i];
}

// ---------------- zero counters ----------------
__global__ void zero_kernel() {
    int i = blockIdx.x * blockDim.x + threadIdx.x;
    if (i < N_NODES) { g_cnt[i] = 0; g_cur[i] = 0; }
}

// ---------------- weight prep ----------------
__global__ void prep_B_kernel(const float* __restrict__ W1_l, const float* __restrict__ W1_r,
                              const float* __restrict__ W2_l, const float* __restrict__ W2_r) {
    int tid = blockIdx.x * blockDim.x + threadIdx.x;
    int nthr = gridDim.x * blockDim.x;
    for (int i = tid; i < 256 * 256; i += nthr) {
        int n = i >> 8, k = i & 255;
        float w = (k < 128) ? W1_l[k * 256 + n] : W1_r[(k - 128) * 256 + n];
        __nv_bfloat16 h = __float2bfloat16(w);
        g_B1_hi[i] = h;
        g_B1_lo[i] = __float2bfloat16(w - __bfloat162float(h));
    }
    for (int i = tid; i < 256 * 512; i += nthr) {
        int n = i >> 9, k = i & 511;
        float w = (k < 256) ? W2_l[k * 256 + n] : W2_r[(k - 256) * 256 + n];
        __nv_bfloat16 h = __float2bfloat16(w);
        g_B2_hi[i] = h;
        g_B2_lo[i] = __float2bfloat16(w - __bfloat162float(h));
    }
}

// ---------------- degree histogram ----------------
__global__ void degree_kernel(const void* __restrict__ ei, int E) {
    int e = blockIdx.x * blockDim.x + threadIdx.x;
    if (e < E) {
        int d = edge_at(ei, (size_t)E + e);
        if (d >= 0 && d < N_NODES) atomicAdd(&g_cnt[d], 1);
    }
}

// ---------------- scan ----------------
__global__ void scan1_kernel(int n) {
    __shared__ int sh[1024];
    int i = blockIdx.x * 1024 + threadIdx.x;
    int v = (i < n) ? g_cnt[i] : 0;
    sh[threadIdx.x] = v;
    __syncthreads();
    #pragma unroll
    for (int o = 1; o < 1024; o <<= 1) {
        int add = (threadIdx.x >= o) ? sh[threadIdx.x - o] : 0;
        __syncthreads();
        sh[threadIdx.x] += add;
        __syncthreads();
    }
    if (i < n) g_rowptr[i] = sh[threadIdx.x] - v;
    if (threadIdx.x == 1023) g_bsum[blockIdx.x] = sh[1023];
}

__global__ void scan2_kernel(int nblocks) {
    if (threadIdx.x == 0) {
        int acc = 0;
        for (int b = 0; b < nblocks; b++) {
            int v = g_bsum[b];
            g_bsum[b] = acc;
            acc += v;
        }
    }
}

__global__ void scan3_kernel(int n, int E) {
    int i = blockIdx.x * 1024 + threadIdx.x;
    if (i < n) g_rowptr[i] += g_bsum[blockIdx.x];
    if (i == 0) g_rowptr[n] = E;
}

// ---------------- CSR fill ----------------
__global__ void fill_kernel(const void* __restrict__ ei, int E) {
    int e = blockIdx.x * blockDim.x + threadIdx.x;
    if (e >= E) return;
    int src = edge_at(ei, e);
    int dst = edge_at(ei, (size_t)E + e);
    if ((unsigned)src >= N_NODES || (unsigned)dst >= N_NODES) return;
    int pos = g_rowptr[dst] + atomicAdd(&g_cur[dst], 1);
    g_esrc[pos] = src;
}

// ---------------- gather aggregation -> packed bf16 hi/lo ----------------
// warp per node; unroll x2; LAYER1 also converts self row (x) into cols 128..255
template<int LAYER>
__global__ void gather_kernel(const float* __restrict__ xext, int n_nodes) {
    constexpr int F = (LAYER == 1) ? F_IN : F_H;
    constexpr int RSTRIDE = (LAYER == 1) ? 128 : 256;
    const float* feat = (LAYER == 1) ? xext : (const float*)g_h1;
    uint32_t* Ahi = (LAYER == 1) ? g_A1hi : g_A2hi;
    uint32_t* Alo = (LAYER == 1) ? g_A1lo : g_A2lo;

    int node = (blockIdx.x * blockDim.x + threadIdx.x) >> 5;
    int lane = threadIdx.x & 31;
    if (node >= n_nodes) return;
    int beg = g_rowptr[node], end = g_rowptr[node + 1];
    float inv = 1.0f / fmaxf((float)(end - beg), 1.0f);

    if (LAYER == 1) {
        float4 acc0 = make_float4(0.f, 0.f, 0.f, 0.f);
        float4 acc1 = make_float4(0.f, 0.f, 0.f, 0.f);
        int i = beg;
        for (; i + 1 < end; i += 2) {
            int sA = __ldg(&g_esrc[i]);
            int sB = __ldg(&g_esrc[i + 1]);
            float4 vA = __ldg((const float4*)(feat + (size_t)sA * F) + lane);
            float4 vB = __ldg((const float4*)(feat + (size_t)sB * F) + lane);
            acc0.x += vA.x; acc0.y += vA.y; acc0.z += vA.z; acc0.w += vA.w;
            acc1.x += vB.x; acc1.y += vB.y; acc1.z += vB.z; acc1.w += vB.w;
        }
        if (i < end) {
            int sA = __ldg(&g_esrc[i]);
            float4 vA = __ldg((const float4*)(feat + (size_t)sA * F) + lane);
            acc0.x += vA.x; acc0.y += vA.y; acc0.z += vA.z; acc0.w += vA.w;
        }
        float a0 = (acc0.x + acc1.x) * inv, a1 = (acc0.y + acc1.y) * inv;
        float a2 = (acc0.z + acc1.z) * inv, a3 = (acc0.w + acc1.w) * inv;
        size_t idx = (size_t)node * RSTRIDE + lane * 2;
        Ahi[idx]     = pack_bf16(a0, a1);
        Ahi[idx + 1] = pack_bf16(a2, a3);
        Alo[idx]     = pack_bf16(a0 - bf16_round(a0), a1 - bf16_round(a1));
        Alo[idx + 1] = pack_bf16(a2 - bf16_round(a2), a3 - bf16_round(a3));
        // self half (cols 128..255): convert x[node]
        float4 v = __ldg((const float4*)(xext + (size_t)node * F) + lane);
        size_t sx = (size_t)node * RSTRIDE + 64 + lane * 2;
        Ahi[sx]     = pack_bf16(v.x, v.y);
        Ahi[sx + 1] = pack_bf16(v.z, v.w);
        Alo[sx]     = pack_bf16(v.x - bf16_round(v.x), v.y - bf16_round(v.y));
        Alo[sx + 1] = pack_bf16(v.z - bf16_round(v.z), v.w - bf16_round(v.w));
    } else {
        float4 p0 = make_float4(0.f, 0.f, 0.f, 0.f);
        float4 p1 = make_float4(0.f, 0.f, 0.f, 0.f);
        float4 q0 = make_float4(0.f, 0.f, 0.f, 0.f);
        float4 q1 = make_float4(0.f, 0.f, 0.f, 0.f);
        int i = beg;
        for (; i + 1 < end; i += 2) {
            int sA = __ldg(&g_esrc[i]);
            int sB = __ldg(&g_esrc[i + 1]);
            const float4* rA = (const float4*)(feat + (size_t)sA * F);
            const float4* rB = (const float4*)(feat + (size_t)sB * F);
            float4 a0 = __ldg(rA + lane),      b0 = __ldg(rB + lane);
            float4 a1 = __ldg(rA + lane + 32), b1 = __ldg(rB + lane + 32);
            p0.x += a0.x; p0.y += a0.y; p0.z += a0.z; p0.w += a0.w;
            q0.x += b0.x; q0.y += b0.y; q0.z += b0.z; q0.w += b0.w;
            p1.x += a1.x; p1.y += a1.y; p1.z += a1.z; p1.w += a1.w;
            q1.x += b1.x; q1.y += b1.y; q1.z += b1.z; q1.w += b1.w;
        }
        if (i < end) {
            int sA = __ldg(&g_esrc[i]);
            const float4* rA = (const float4*)(feat + (size_t)sA * F);
            float4 a0 = __ldg(rA + lane);
            float4 a1 = __ldg(rA + lane + 32);
            p0.x += a0.x; p0.y += a0.y; p0.z += a0.z; p0.w += a0.w;
            p1.x += a1.x; p1.y += a1.y; p1.z += a1.z; p1.w += a1.w;
        }
        float b0 = (p0.x + q0.x) * inv, b1 = (p0.y + q0.y) * inv;
        float b2 = (p0.z + q0.z) * inv, b3 = (p0.w + q0.w) * inv;
        float c0 = (p1.x + q1.x) * inv, c1 = (p1.y + q1.y) * inv;
        float c2 = (p1.z + q1.z) * inv, c3 = (p1.w + q1.w) * inv;
        size_t i0 = (size_t)node * RSTRIDE + lane * 2;
        size_t i1 = i0 + 64;
        Ahi[i0]     = pack_bf16(b0, b1);
        Ahi[i0 + 1] = pack_bf16(b2, b3);
        Ahi[i1]     = pack_bf16(c0, c1);
        Ahi[i1 + 1] = pack_bf16(c2, c3);
        Alo[i0]     = pack_bf16(b0 - bf16_round(b0), b1 - bf16_round(b1));
        Alo[i0 + 1] = pack_bf16(b2 - bf16_round(b2), b3 - bf16_round(b3));
        Alo[i1]     = pack_bf16(c0 - bf16_round(c0), c1 - bf16_round(c1));
        Alo[i1 + 1] = pack_bf16(c2 - bf16_round(c2), c3 - bf16_round(c3));
    }
}

// ================= warp-level bf16 MMA GEMM, cp.async + ldmatrix =============
__device__ __forceinline__ void mma16816(float* c, const uint32_t* a, const uint32_t* b) {
    asm volatile(
        "mma.sync.aligned.m16n8k16.row.col.f32.bf16.bf16.f32 "
        "{%0,%1,%2,%3}, {%4,%5,%6,%7}, {%8,%9}, {%0,%1,%2,%3};"
        : "+f"(c[0]), "+f"(c[1]), "+f"(c[2]), "+f"(c[3])
        : "r"(a[0]), "r"(a[1]), "r"(a[2]), "r"(a[3]), "r"(b[0]), "r"(b[1]));
}

__device__ __forceinline__ void ldsm_x4(uint32_t* r, uint32_t addr) {
    asm volatile("ldmatrix.sync.aligned.m8n8.x4.shared.b16 {%0,%1,%2,%3}, [%4];"
        : "=r"(r[0]), "=r"(r[1]), "=r"(r[2]), "=r"(r[3]) : "r"(addr));
}
__device__ __forceinline__ void ldsm_x2(uint32_t* r, uint32_t addr) {
    asm volatile("ldmatrix.sync.aligned.m8n8.x2.shared.b16 {%0,%1}, [%2];"
        : "=r"(r[0]), "=r"(r[1]) : "r"(addr));
}

__device__ __forceinline__ void cp16(uint32_t smem_byte, const void* gmem) {
    asm volatile("cp.async.cg.shared.global [%0], [%1], 16;" :: "r"(smem_byte), "l"(gmem));
}

#define SM_AH 0
#define SM_AL 2560
#define SM_BH 5120
#define SM_BL 10240
#define STG_U32 15360
#define SMEM_MMA (2 * STG_U32 * 4)

template<int LAYER>
__global__ void __launch_bounds__(256, 1)
mma_gemm_kernel(const float* __restrict__ bias,
                const float* __restrict__ gamma, const float* __restrict__ beta,
                const float* __restrict__ mu,    const float* __restrict__ var,
                float* __restrict__ outp, int n_rows)
{
    constexpr int KTOT = (LAYER == 1) ? 256 : 512;
    constexpr int NCH  = KTOT / 32;
    constexpr int RS   = KTOT / 2;
    const uint32_t* Ahi = (LAYER == 1) ? g_A1hi : g_A2hi;
    const uint32_t* Alo = (LAYER == 1) ? g_A1lo : g_A2lo;
    const __nv_bfloat16* Bhi = (LAYER == 1) ? g_B1_hi : g_B2_hi;
    const __nv_bfloat16* Blo = (LAYER == 1) ? g_B1_lo : g_B2_lo;
    float* out = (LAYER == 1) ? g_h1 : outp;

    extern __shared__ uint32_t smu[];
    __shared__ float s_scale[256], s_shift[256];
    __shared__ float s_ss[128];

    const int t = threadIdx.x, wid = t >> 5, lane = t & 31;
    const int grp = lane >> 2, tig = lane & 3;
    const int wm = wid & 3, wn = wid >> 2;
    const int row0 = blockIdx.x * 128;

    uint32_t smem_base;
    asm("{ .reg .u64 tt; cvta.to.shared.u64 tt, %1; cvt.u32.u64 %0, tt; }"
        : "=r"(smem_base) : "l"(smu));

    if (LAYER == 1) {
        float s = gamma[t] * rsqrtf(var[t] + BN_EPS);
        s_scale[t] = s;
        s_shift[t] = beta[t] + (bias[t] - mu[t]) * s;
    } else {
        s_scale[t] = 1.0f;
        s_shift[t] = bias[t];
    }
    if (t < 128) s_ss[t] = 0.0f;

    auto load_chunk = [&](int ch, int stg) {
        uint32_t sb = smem_base + stg * (STG_U32 * 4);
        #pragma unroll
        for (int l = 0; l < 2; l++) {
            int id = t + l * 256;
            int r = id >> 2, q = id & 3;
            int gr = row0 + r;
            if (gr >= n_rows) gr = n_rows - 1;
            size_t off = ((size_t)gr * RS + ch * 16 + q * 4) * 4;
            cp16(sb + (SM_AH + r * 20 + q * 4) * 4, (const char*)Ahi + off);
            cp16(sb + (SM_AL + r * 20 + q * 4) * 4, (const char*)Alo + off);
        }
        #pragma unroll
        for (int l = 0; l < 4; l++) {
            int id = t + l * 256;
            int n = id >> 2, q = id & 3;
            size_t off = ((size_t)n * KTOT + ch * 32) * 2 + q * 16;
            cp16(sb + (SM_BH + n * 20 + q * 4) * 4, (const char*)Bhi + off);
            cp16(sb + (SM_BL + n * 20 + q * 4) * 4, (const char*)Blo + off);
        }
        asm volatile("cp.async.commit_group;");
    };

    float acc[2][16][4];
    #pragma unroll
    for (int mt = 0; mt < 2; mt++)
        #pragma unroll
        for (int nt = 0; nt < 16; nt++)
            #pragma unroll
            for (int q = 0; q < 4; q++) acc[mt][nt][q] = 0.0f;

    // ldmatrix per-lane address components
    const int a_row_in_tile = (lane & 7) + ((lane >> 3) & 1) * 8;   // + mt*16 + wm*32
    const int a_kof4 = ((lane >> 4) & 1) * 4;                        // + pb
    const int b_row_in_tile = (lane & 7);                            // + nt*8 + wn*128
    const int b_kof4 = ((lane >> 3) & 1) * 4;                        // + pb

    load_chunk(0, 0);

    for (int ch = 0; ch < NCH; ch++) {
        if (ch + 1 < NCH) {
            load_chunk(ch + 1, (ch + 1) & 1);
            asm volatile("cp.async.wait_group 1;");
        } else {
            asm volatile("cp.async.wait_group 0;");
        }
        __syncthreads();

        uint32_t sb = smem_base + (ch & 1) * (STG_U32 * 4);
        #pragma unroll
        for (int s16 = 0; s16 < 2; s16++) {
            const int pb = s16 * 8;
            uint32_t ah[2][4], al[2][4];
            #pragma unroll
            for (int mt = 0; mt < 2; mt++) {
                int row = wm * 32 + mt * 16 + a_row_in_tile;
                uint32_t addr = sb + (row * 20 + pb + a_kof4) * 4;
                ldsm_x4(ah[mt], addr + SM_AH * 4);
                ldsm_x4(al[mt], addr + SM_AL * 4);
            }
            uint32_t baddr0 = sb + ((wn * 128 + b_row_in_tile) * 20 + pb + b_kof4) * 4;
            #pragma unroll
            for (int nt = 0; nt < 16; nt++) {
                uint32_t baddr = baddr0 + nt * 8 * 20 * 4;
                uint32_t bh[2], bl[2];
                ldsm_x2(bh, baddr + SM_BH * 4);
                ldsm_x2(bl, baddr + SM_BL * 4);
                #pragma unroll
                for (int mt = 0; mt < 2; mt++) {
                    mma16816(acc[mt][nt], ah[mt], bh);
                    mma16816(acc[mt][nt], ah[mt], bl);
                    mma16816(acc[mt][nt], al[mt], bh);
                }
            }
        }
        __syncthreads();
    }

    if (LAYER == 1) {
        // epilogue: BN+ReLU, write h1 + A2 self half
        #pragma unroll
        for (int mt = 0; mt < 2; mt++) {
            int r_lo = row0 + wm * 32 + mt * 16 + grp;
            int r_hi = r_lo + 8;
            #pragma unroll
            for (int nt = 0; nt < 16; nt++) {
                int c = wn * 128 + nt * 8 + 2 * tig;
                float s0 = s_scale[c],   sh0 = s_shift[c];
                float s1 = s_scale[c+1], sh1 = s_shift[c+1];
                if (r_lo < n_rows) {
                    float v0 = fmaxf(fmaf(acc[mt][nt][0], s0, sh0), 0.f);
                    float v1 = fmaxf(fmaf(acc[mt][nt][1], s1, sh1), 0.f);
                    *(float2*)(out + (size_t)r_lo * 256 + c) = make_float2(v0, v1);
                    size_t ai = (size_t)r_lo * 256 + 128 + (c >> 1);
                    g_A2hi[ai] = pack_bf16(v0, v1);
                    g_A2lo[ai] = pack_bf16(v0 - bf16_round(v0), v1 - bf16_round(v1));
                }
                if (r_hi < n_rows) {
                    float v2 = fmaxf(fmaf(acc[mt][nt][2], s0, sh0), 0.f);
                    float v3 = fmaxf(fmaf(acc[mt][nt][3], s1, sh1), 0.f);
                    *(float2*)(out + (size_t)r_hi * 256 + c) = make_float2(v2, v3);
                    size_t ai = (size_t)r_hi * 256 + 128 + (c >> 1);
                    g_A2hi[ai] = pack_bf16(v2, v3);
                    g_A2lo[ai] = pack_bf16(v2 - bf16_round(v2), v3 - bf16_round(v3));
                }
            }
        }
    } else {
        // epilogue with fused L2 norm: add bias, reduce sum-of-squares per row,
        // normalize, store once.
        float ssl[2] = {0.f, 0.f}, ssh[2] = {0.f, 0.f};
        #pragma unroll
        for (int mt = 0; mt < 2; mt++) {
            #pragma unroll
            for (int nt = 0; nt < 16; nt++) {
                int c = wn * 128 + nt * 8 + 2 * tig;
                float v0 = acc[mt][nt][0] + s_shift[c];
                float v1 = acc[mt][nt][1] + s_shift[c + 1];
                float v2 = acc[mt][nt][2] + s_shift[c];
                float v3 = acc[mt][nt][3] + s_shift[c + 1];
                ssl[mt] += v0 * v0 + v1 * v1;
                ssh[mt] += v2 * v2 + v3 * v3;
            }
        }
        // reduce over the 4 lanes sharing a row (tig)
        #pragma unroll
        for (int mt = 0; mt < 2; mt++) {
            #pragma unroll
            for (int o = 1; o < 4; o <<= 1) {
                ssl[mt] += __shfl_xor_sync(0xFFFFFFFFu, ssl[mt], o);
                ssh[mt] += __shfl_xor_sync(0xFFFFFFFFu, ssh[mt], o);
            }
        }
        if (tig == 0) {
            #pragma unroll
            for (int mt = 0; mt < 2; mt++) {
                atomicAdd(&s_ss[wm * 32 + mt * 16 + grp], ssl[mt]);
                atomicAdd(&s_ss[wm * 32 + mt * 16 + grp + 8], ssh[mt]);
            }
        }
        __syncthreads();
        #pragma unroll
        for (int mt = 0; mt < 2; mt++) {
            int lr = wm * 32 + mt * 16 + grp;
            int r_lo = row0 + lr, r_hi = r_lo + 8;
            float invlo = 1.0f / fmaxf(sqrtf(s_ss[lr]), L2_EPS);
            float invhi = 1.0f / fmaxf(sqrtf(s_ss[lr + 8]), L2_EPS);
            #pragma unroll
            for (int nt = 0; nt < 16; nt++) {
                int c = wn * 128 + nt * 8 + 2 * tig;
                if (r_lo < n_rows) {
                    float v0 = (acc[mt][nt][0] + s_shift[c]) * invlo;
                    float v1 = (acc[mt][nt][1] + s_shift[c + 1]) * invlo;
                    *(float2*)(out + (size_t)r_lo * 256 + c) = make_float2(v0, v1);
                }
                if (r_hi < n_rows) {
                    float v2 = (acc[mt][nt][2] + s_shift[c]) * invhi;
                    float v3 = (acc[mt][nt][3] + s_shift[c + 1]) * invhi;
                    *(float2*)(out + (size_t)r_hi * 256 + c) = make_float2(v2, v3);
                }
            }
        }
    }
}

// ---------------- launch ----------------
extern "C" void kernel_launch(void* const* d_in, const int* in_sizes, int n_in,
                              void* d_out, int out_size) {
    const float* x      = (const float*)d_in[0];
    const void*  ei     = d_in[1];
    const float* W1_l   = (const float*)d_in[2];
    const float* b1_l   = (const float*)d_in[3];
    const float* W1_r   = (const float*)d_in[4];
    const float* gamma  = (const float*)d_in[5];
    const float* beta   = (const float*)d_in[6];
    const float* mu     = (const float*)d_in[7];
    const float* var    = (const float*)d_in[8];
    const float* W2_l   = (const float*)d_in[9];
    const float* b2_l   = (const float*)d_in[10];
    const float* W2_r   = (const float*)d_in[11];
    float* out = (float*)d_out;

    const int N = in_sizes[0] / F_IN;     // 100000
    const int E = in_sizes[1] / 2;        // 800000
    const int nsb = (N + 1023) / 1024;

    cudaFuncSetAttribute(mma_gemm_kernel<1>, cudaFuncAttributeMaxDynamicSharedMemorySize, SMEM_MMA);
    cudaFuncSetAttribute(mma_gemm_kernel<2>, cudaFuncAttributeMaxDynamicSharedMemorySize, SMEM_MMA);

    detect_kernel<<<1, 128>>>((const int*)ei);
    zero_kernel<<<(N + 255) / 256, 256>>>();
    prep_B_kernel<<<512, 256>>>(W1_l, W1_r, W2_l, W2_r);

    // CSR build
    degree_kernel<<<(E + 255) / 256, 256>>>(ei, E);
    scan1_kernel<<<nsb, 1024>>>(N);
    scan2_kernel<<<1, 32>>>(nsb);
    scan3_kernel<<<nsb, 1024>>>(N, E);
    fill_kernel<<<(E + 255) / 256, 256>>>(ei, E);

    // layer-1: A1 = [mean(x nbrs) | x]
    gather_kernel<1><<<(N * 32 + 255) / 256, 256>>>(x, N);

    // h1 = relu(BN(A1 @ B1)) -> g_h1 (+ A2 self half)
    {
        int tiles = (N + 127) / 128;
        mma_gemm_kernel<1><<<tiles, 256, SMEM_MMA>>>(b1_l, gamma, beta, mu, var, nullptr, N);
    }

    // layer-2: A2[:, 0:256] = mean(h1 nbrs)
    gather_kernel<2><<<(N * 32 + 255) / 256, 256>>>(nullptr, N);

    // out = l2norm(A2 @ B2 + b2)
    {
        int tiles = (N + 127) / 128;
        mma_gemm_kernel<2><<<tiles, 256, SMEM_MMA>>>(b2_l, nullptr, nullptr, nullptr, nullptr, out, N);
    }
}

// round 12
// speedup vs baseline: 3.5639x; 1.2280x over previous
#include <cuda_runtime.h>
#include <cuda_fp16.h>
#include <cstdint>

#define N_NODES 100000
#define E_MAX   800000
#define F_IN 128
#define F_H  256
#define BN_EPS 1e-5f
#define L2_EPS 1e-12f

// ---------------- scratch (device globals; referenced ONLY from device code) --
// h1 stored as packed fp16 (u32 = 2 halves): [N][128] u32
__device__ __align__(16) uint32_t g_h1h[(size_t)N_NODES * 128];
// A matrices packed fp16: A1 [N][128] u32 (agg128|self128), A2 [N][256] u32
__device__ __align__(16) uint32_t g_A1[(size_t)N_NODES * 128];
__device__ __align__(16) uint32_t g_A2[(size_t)N_NODES * 256];
__device__ int   g_cnt[N_NODES];
__device__ int   g_cur[N_NODES];
__device__ int   g_rowptr[N_NODES + 1];
__device__ int   g_bsum[128];
__device__ int   g_esrc[E_MAX];
__device__ int   g_is64;

// weights transposed fp16: B[n][k], n = out col (256), k = in
__device__ __align__(16) __half g_B1[256 * 256];
__device__ __align__(16) __half g_B2[256 * 512];

// ---------------- helpers ----------------
__device__ __forceinline__ uint32_t pack_f16(float x, float y) {
    __half2 h = __floats2half2_rn(x, y);
    return *(uint32_t*)&h;
}

// ---------------- edge-index dtype detection ----------------
__global__ void detect_kernel(const int* __restrict__ ei_raw) {
    __shared__ int any_nonzero;
    if (threadIdx.x == 0) any_nonzero = 0;
    __syncthreads();
    int w = ei_raw[threadIdx.x * 2 + 1];
    if (w != 0) atomicOr(&any_nonzero, 1);
    __syncthreads();
    if (threadIdx.x == 0) g_is64 = any_nonzero ? 0 : 1;
}

__device__ __forceinline__ int edge_at(const void* ei, size_t i) {
    if (g_is64) return (int)((const long long*)ei)[i];
    return ((const int*)ei)[i];
}

// ---------------- zero counters ----------------
__global__ void zero_kernel() {
    int i = blockIdx.x * blockDim.x + threadIdx.x;
    if (i < N_NODES) { g_cnt[i] = 0; g_cur[i] = 0; }
}

// ---------------- weight prep: transpose + fp16 ----------------
__global__ void prep_B_kernel(const float* __restrict__ W1_l, const float* __restrict__ W1_r,
                              const float* __restrict__ W2_l, const float* __restrict__ W2_r) {
    int tid = blockIdx.x * blockDim.x + threadIdx.x;
    int nthr = gridDim.x * blockDim.x;
    for (int i = tid; i < 256 * 256; i += nthr) {
        int n = i >> 8, k = i & 255;
        float w = (k < 128) ? W1_l[k * 256 + n] : W1_r[(k - 128) * 256 + n];
        g_B1[i] = __float2half_rn(w);
    }
    for (int i = tid; i < 256 * 512; i += nthr) {
        int n = i >> 9, k = i & 511;
        float w = (k < 256) ? W2_l[k * 256 + n] : W2_r[(k - 256) * 256 + n];
        g_B2[i] = __float2half_rn(w);
    }
}

// ---------------- degree histogram ----------------
__global__ void degree_kernel(const void* __restrict__ ei, int E) {
    int e = blockIdx.x * blockDim.x + threadIdx.x;
    if (e < E) {
        int d = edge_at(ei, (size_t)E + e);
        if (d >= 0 && d < N_NODES) atomicAdd(&g_cnt[d], 1);
    }
}

// ---------------- scan ----------------
__global__ void scan1_kernel(int n) {
    __shared__ int sh[1024];
    int i = blockIdx.x * 1024 + threadIdx.x;
    int v = (i < n) ? g_cnt[i] : 0;
    sh[threadIdx.x] = v;
    __syncthreads();
    #pragma unroll
    for (int o = 1; o < 1024; o <<= 1) {
        int add = (threadIdx.x >= o) ? sh[threadIdx.x - o] : 0;
        __syncthreads();
        sh[threadIdx.x] += add;
        __syncthreads();
    }
    if (i < n) g_rowptr[i] = sh[threadIdx.x] - v;
    if (threadIdx.x == 1023) g_bsum[blockIdx.x] = sh[1023];
}

__global__ void scan2_kernel(int nblocks) {
    if (threadIdx.x == 0) {
        int acc = 0;
        for (int b = 0; b < nblocks; b++) {
            int v = g_bsum[b];
            g_bsum[b] = acc;
            acc += v;
        }
    }
}

__global__ void scan3_kernel(int n, int E) {
    int i = blockIdx.x * 1024 + threadIdx.x;
    if (i < n) g_rowptr[i] += g_bsum[blockIdx.x];
    if (i == 0) g_rowptr[n] = E;
}

// ---------------- CSR fill ----------------
__global__ void fill_kernel(const void* __restrict__ ei, int E) {
    int e = blockIdx.x * blockDim.x + threadIdx.x;
    if (e >= E) return;
    int src = edge_at(ei, e);
    int dst = edge_at(ei, (size_t)E + e);
    if ((unsigned)src >= N_NODES || (unsigned)dst >= N_NODES) return;
    int pos = g_rowptr[dst] + atomicAdd(&g_cur[dst], 1);
    g_esrc[pos] = src;
}

// ---------------- gather layer 1: x (fp32) -> A1 packed fp16 ----------------
__global__ void gather1_kernel(const float* __restrict__ x, int n_nodes) {
    int node = (blockIdx.x * blockDim.x + threadIdx.x) >> 5;
    int lane = threadIdx.x & 31;
    if (node >= n_nodes) return;
    int beg = g_rowptr[node], end = g_rowptr[node + 1];
    float inv = 1.0f / fmaxf((float)(end - beg), 1.0f);

    float4 acc0 = make_float4(0.f, 0.f, 0.f, 0.f);
    float4 acc1 = make_float4(0.f, 0.f, 0.f, 0.f);
    int i = beg;
    for (; i + 1 < end; i += 2) {
        int sA = __ldg(&g_esrc[i]);
        int sB = __ldg(&g_esrc[i + 1]);
        float4 vA = __ldg((const float4*)(x + (size_t)sA * F_IN) + lane);
        float4 vB = __ldg((const float4*)(x + (size_t)sB * F_IN) + lane);
        acc0.x += vA.x; acc0.y += vA.y; acc0.z += vA.z; acc0.w += vA.w;
        acc1.x += vB.x; acc1.y += vB.y; acc1.z += vB.z; acc1.w += vB.w;
    }
    if (i < end) {
        int sA = __ldg(&g_esrc[i]);
        float4 vA = __ldg((const float4*)(x + (size_t)sA * F_IN) + lane);
        acc0.x += vA.x; acc0.y += vA.y; acc0.z += vA.z; acc0.w += vA.w;
    }
    float a0 = (acc0.x + acc1.x) * inv, a1 = (acc0.y + acc1.y) * inv;
    float a2 = (acc0.z + acc1.z) * inv, a3 = (acc0.w + acc1.w) * inv;
    size_t idx = (size_t)node * 128 + lane * 2;
    g_A1[idx]     = pack_f16(a0, a1);
    g_A1[idx + 1] = pack_f16(a2, a3);
    // self half (cols 128..255)
    float4 v = __ldg((const float4*)(x + (size_t)node * F_IN) + lane);
    g_A1[idx + 64]     = pack_f16(v.x, v.y);
    g_A1[idx + 64 + 1] = pack_f16(v.z, v.w);
}

// ---------------- gather layer 2: h1 (packed fp16) -> A2 agg half -----------
__global__ void gather2_kernel(int n_nodes) {
    int node = (blockIdx.x * blockDim.x + threadIdx.x) >> 5;
    int lane = threadIdx.x & 31;
    if (node >= n_nodes) return;
    int beg = g_rowptr[node], end = g_rowptr[node + 1];
    float inv = 1.0f / fmaxf((float)(end - beg), 1.0f);

    float acc[8] = {0.f, 0.f, 0.f, 0.f, 0.f, 0.f, 0.f, 0.f};
    float accB[8] = {0.f, 0.f, 0.f, 0.f, 0.f, 0.f, 0.f, 0.f};
    int i = beg;
    for (; i + 1 < end; i += 2) {
        int sA = __ldg(&g_esrc[i]);
        int sB = __ldg(&g_esrc[i + 1]);
        uint4 vA = __ldg((const uint4*)(g_h1h + (size_t)sA * 128) + lane);
        uint4 vB = __ldg((const uint4*)(g_h1h + (size_t)sB * 128) + lane);
        const __half2* hA = (const __half2*)&vA;
        const __half2* hB = (const __half2*)&vB;
        #pragma unroll
        for (int q = 0; q < 4; q++) {
            float2 fA = __half22float2(hA[q]);
            float2 fB = __half22float2(hB[q]);
            acc[q * 2] += fA.x;  acc[q * 2 + 1] += fA.y;
            accB[q * 2] += fB.x; accB[q * 2 + 1] += fB.y;
        }
    }
    if (i < end) {
        int sA = __ldg(&g_esrc[i]);
        uint4 vA = __ldg((const uint4*)(g_h1h + (size_t)sA * 128) + lane);
        const __half2* hA = (const __half2*)&vA;
        #pragma unroll
        for (int q = 0; q < 4; q++) {
            float2 fA = __half22float2(hA[q]);
            acc[q * 2] += fA.x; acc[q * 2 + 1] += fA.y;
        }
    }
    uint32_t outw[4];
    #pragma unroll
    for (int q = 0; q < 4; q++)
        outw[q] = pack_f16((acc[q * 2] + accB[q * 2]) * inv,
                           (acc[q * 2 + 1] + accB[q * 2 + 1]) * inv);
    *((uint4*)(g_A2 + (size_t)node * 256) + lane) = *(uint4*)outw;
}

// ================= warp-level fp16 MMA GEMM, cp.async + ldmatrix =============
__device__ __forceinline__ void mma16816(float* c, const uint32_t* a, const uint32_t* b) {
    asm volatile(
        "mma.sync.aligned.m16n8k16.row.col.f32.f16.f16.f32 "
        "{%0,%1,%2,%3}, {%4,%5,%6,%7}, {%8,%9}, {%0,%1,%2,%3};"
        : "+f"(c[0]), "+f"(c[1]), "+f"(c[2]), "+f"(c[3])
        : "r"(a[0]), "r"(a[1]), "r"(a[2]), "r"(a[3]), "r"(b[0]), "r"(b[1]));
}

__device__ __forceinline__ void ldsm_x4(uint32_t* r, uint32_t addr) {
    asm volatile("ldmatrix.sync.aligned.m8n8.x4.shared.b16 {%0,%1,%2,%3}, [%4];"
        : "=r"(r[0]), "=r"(r[1]), "=r"(r[2]), "=r"(r[3]) : "r"(addr));
}
__device__ __forceinline__ void ldsm_x2(uint32_t* r, uint32_t addr) {
    asm volatile("ldmatrix.sync.aligned.m8n8.x2.shared.b16 {%0,%1}, [%2];"
        : "=r"(r[0]), "=r"(r[1]) : "r"(addr));
}

__device__ __forceinline__ void cp16(uint32_t smem_byte, const void* gmem) {
    asm volatile("cp.async.cg.shared.global [%0], [%1], 16;" :: "r"(smem_byte), "l"(gmem));
}

// stage layout (u32): A@0 (128x20), B@2560 (256x20)
#define SM_A 0
#define SM_B 2560
#define STG_U32 7680
#define SMEM_MMA (2 * STG_U32 * 4)     // 61440 B

template<int LAYER>
__global__ void __launch_bounds__(256, 1)
mma_gemm_kernel(const float* __restrict__ bias,
                const float* __restrict__ gamma, const float* __restrict__ beta,
                const float* __restrict__ mu,    const float* __restrict__ var,
                float* __restrict__ outp, int n_rows)
{
    constexpr int KTOT = (LAYER == 1) ? 256 : 512;
    constexpr int NCH  = KTOT / 32;
    constexpr int RS   = KTOT / 2;        // A row stride in u32 (2 halves per u32)
    const uint32_t* A = (LAYER == 1) ? g_A1 : g_A2;
    const __half* B   = (LAYER == 1) ? g_B1 : g_B2;

    extern __shared__ uint32_t smu[];
    __shared__ float s_scale[256], s_shift[256];
    __shared__ float s_ss[128];

    const int t = threadIdx.x, wid = t >> 5, lane = t & 31;
    const int grp = lane >> 2, tig = lane & 3;
    const int wm = wid & 3, wn = wid >> 2;
    const int row0 = blockIdx.x * 128;

    uint32_t smem_base;
    asm("{ .reg .u64 tt; cvta.to.shared.u64 tt, %1; cvt.u32.u64 %0, tt; }"
        : "=r"(smem_base) : "l"(smu));

    if (LAYER == 1) {
        float s = gamma[t] * rsqrtf(var[t] + BN_EPS);
        s_scale[t] = s;
        s_shift[t] = beta[t] + (bias[t] - mu[t]) * s;
    } else {
        s_scale[t] = 1.0f;
        s_shift[t] = bias[t];
    }
    if (t < 128) s_ss[t] = 0.0f;

    auto load_chunk = [&](int ch, int stg) {
        uint32_t sb = smem_base + stg * (STG_U32 * 4);
        #pragma unroll
        for (int l = 0; l < 2; l++) {
            int id = t + l * 256;          // 0..511
            int r = id >> 2, q = id & 3;
            int gr = row0 + r;
            if (gr >= n_rows) gr = n_rows - 1;
            size_t off = ((size_t)gr * RS + ch * 16 + q * 4) * 4;
            cp16(sb + (SM_A + r * 20 + q * 4) * 4, (const char*)A + off);
        }
        #pragma unroll
        for (int l = 0; l < 4; l++) {
            int id = t + l * 256;          // 0..1023
            int n = id >> 2, q = id & 3;
            size_t off = ((size_t)n * KTOT + ch * 32) * 2 + q * 16;
            cp16(sb + (SM_B + n * 20 + q * 4) * 4, (const char*)B + off);
        }
        asm volatile("cp.async.commit_group;");
    };

    float acc[2][16][4];
    #pragma unroll
    for (int mt = 0; mt < 2; mt++)
        #pragma unroll
        for (int nt = 0; nt < 16; nt++)
            #pragma unroll
            for (int q = 0; q < 4; q++) acc[mt][nt][q] = 0.0f;

    const int a_row_in_tile = (lane & 7) + ((lane >> 3) & 1) * 8;
    const int a_kof4 = ((lane >> 4) & 1) * 4;
    const int b_row_in_tile = (lane & 7);
    const int b_kof4 = ((lane >> 3) & 1) * 4;

    load_chunk(0, 0);

    for (int ch = 0; ch < NCH; ch++) {
        if (ch + 1 < NCH) {
            load_chunk(ch + 1, (ch + 1) & 1);
            asm volatile("cp.async.wait_group 1;");
        } else {
            asm volatile("cp.async.wait_group 0;");
        }
        __syncthreads();

        uint32_t sb = smem_base + (ch & 1) * (STG_U32 * 4);
        #pragma unroll
        for (int s16 = 0; s16 < 2; s16++) {
            const int pb = s16 * 8;
            uint32_t ah[2][4];
            #pragma unroll
            for (int mt = 0; mt < 2; mt++) {
                int row = wm * 32 + mt * 16 + a_row_in_tile;
                ldsm_x4(ah[mt], sb + (SM_A + row * 20 + pb + a_kof4) * 4);
            }
            uint32_t baddr0 = sb + (SM_B + (wn * 128 + b_row_in_tile) * 20 + pb + b_kof4) * 4;
            #pragma unroll
            for (int nt = 0; nt < 16; nt++) {
                uint32_t bh[2];
                ldsm_x2(bh, baddr0 + nt * 8 * 20 * 4);
                mma16816(acc[0][nt], ah[0], bh);
                mma16816(acc[1][nt], ah[1], bh);
            }
        }
        __syncthreads();
    }

    if (LAYER == 1) {
        // epilogue: BN+ReLU -> h1 (fp16) + A2 self half (same packed value)
        #pragma unroll
        for (int mt = 0; mt < 2; mt++) {
            int r_lo = row0 + wm * 32 + mt * 16 + grp;
            int r_hi = r_lo + 8;
            #pragma unroll
            for (int nt = 0; nt < 16; nt++) {
                int c = wn * 128 + nt * 8 + 2 * tig;
                float s0 = s_scale[c],   sh0 = s_shift[c];
                float s1 = s_scale[c+1], sh1 = s_shift[c+1];
                if (r_lo < n_rows) {
                    float v0 = fmaxf(fmaf(acc[mt][nt][0], s0, sh0), 0.f);
                    float v1 = fmaxf(fmaf(acc[mt][nt][1], s1, sh1), 0.f);
                    uint32_t pw = pack_f16(v0, v1);
                    g_h1h[(size_t)r_lo * 128 + (c >> 1)] = pw;
                    g_A2[(size_t)r_lo * 256 + 128 + (c >> 1)] = pw;
                }
                if (r_hi < n_rows) {
                    float v2 = fmaxf(fmaf(acc[mt][nt][2], s0, sh0), 0.f);
                    float v3 = fmaxf(fmaf(acc[mt][nt][3], s1, sh1), 0.f);
                    uint32_t pw = pack_f16(v2, v3);
                    g_h1h[(size_t)r_hi * 128 + (c >> 1)] = pw;
                    g_A2[(size_t)r_hi * 256 + 128 + (c >> 1)] = pw;
                }
            }
        }
    } else {
        // epilogue with fused L2 norm
        float ssl[2] = {0.f, 0.f}, ssh[2] = {0.f, 0.f};
        #pragma unroll
        for (int mt = 0; mt < 2; mt++) {
            #pragma unroll
            for (int nt = 0; nt < 16; nt++) {
                int c = wn * 128 + nt * 8 + 2 * tig;
                float v0 = acc[mt][nt][0] + s_shift[c];
                float v1 = acc[mt][nt][1] + s_shift[c + 1];
                float v2 = acc[mt][nt][2] + s_shift[c];
                float v3 = acc[mt][nt][3] + s_shift[c + 1];
                ssl[mt] += v0 * v0 + v1 * v1;
                ssh[mt] += v2 * v2 + v3 * v3;
            }
        }
        #pragma unroll
        for (int mt = 0; mt < 2; mt++) {
            #pragma unroll
            for (int o = 1; o < 4; o <<= 1) {
                ssl[mt] += __shfl_xor_sync(0xFFFFFFFFu, ssl[mt], o);
                ssh[mt] += __shfl_xor_sync(0xFFFFFFFFu, ssh[mt], o);
            }
        }
        if (tig == 0) {
            #pragma unroll
            for (int mt = 0; mt < 2; mt++) {
                atomicAdd(&s_ss[wm * 32 + mt * 16 + grp], ssl[mt]);
                atomicAdd(&s_ss[wm * 32 + mt * 16 + grp + 8], ssh[mt]);
            }
        }
        __syncthreads();
        #pragma unroll
        for (int mt = 0; mt < 2; mt++) {
            int lr = wm * 32 + mt * 16 + grp;
            int r_lo = row0 + lr, r_hi = r_lo + 8;
            float invlo = 1.0f / fmaxf(sqrtf(s_ss[lr]), L2_EPS);
            float invhi = 1.0f / fmaxf(sqrtf(s_ss[lr + 8]), L2_EPS);
            #pragma unroll
            for (int nt = 0; nt < 16; nt++) {
                int c = wn * 128 + nt * 8 + 2 * tig;
                if (r_lo < n_rows) {
                    float v0 = (acc[mt][nt][0] + s_shift[c]) * invlo;
                    float v1 = (acc[mt][nt][1] + s_shift[c + 1]) * invlo;
                    *(float2*)(outp + (size_t)r_lo * 256 + c) = make_float2(v0, v1);
                }
                if (r_hi < n_rows) {
                    float v2 = (acc[mt][nt][2] + s_shift[c]) * invhi;
                    float v3 = (acc[mt][nt][3] + s_shift[c + 1]) * invhi;
                    *(float2*)(outp + (size_t)r_hi * 256 + c) = make_float2(v2, v3);
                }
            }
        }
    }
}

// ---------------- launch ----------------
extern "C" void kernel_launch(void* const* d_in, const int* in_sizes, int n_in,
                              void* d_out, int out_size) {
    const float* x      = (const float*)d_in[0];
    const void*  ei     = d_in[1];
    const float* W1_l   = (const float*)d_in[2];
    const float* b1_l   = (const float*)d_in[3];
    const float* W1_r   = (const float*)d_in[4];
    const float* gamma  = (const float*)d_in[5];
    const float* beta   = (const float*)d_in[6];
    const float* mu     = (const float*)d_in[7];
    const float* var    = (const float*)d_in[8];
    const float* W2_l   = (const float*)d_in[9];
    const float* b2_l   = (const float*)d_in[10];
    const float* W2_r   = (const float*)d_in[11];
    float* out = (float*)d_out;

    const int N = in_sizes[0] / F_IN;     // 100000
    const int E = in_sizes[1] / 2;        // 800000
    const int nsb = (N + 1023) / 1024;

    cudaFuncSetAttribute(mma_gemm_kernel<1>, cudaFuncAttributeMaxDynamicSharedMemorySize, SMEM_MMA);
    cudaFuncSetAttribute(mma_gemm_kernel<2>, cudaFuncAttributeMaxDynamicSharedMemorySize, SMEM_MMA);

    detect_kernel<<<1, 128>>>((const int*)ei);
    zero_kernel<<<(N + 255) / 256, 256>>>();
    prep_B_kernel<<<512, 256>>>(W1_l, W1_r, W2_l, W2_r);

    // CSR build
    degree_kernel<<<(E + 255) / 256, 256>>>(ei, E);
    scan1_kernel<<<nsb, 1024>>>(N);
    scan2_kernel<<<1, 32>>>(nsb);
    scan3_kernel<<<nsb, 1024>>>(N, E);
    fill_kernel<<<(E + 255) / 256, 256>>>(ei, E);

    // layer-1: A1 = [mean(x nbrs) | x]  (fp16 packed)
    gather1_kernel<<<(N * 32 + 255) / 256, 256>>>(x, N);

    // h1 = relu(BN(A1 @ B1)) -> g_h1h fp16 (+ A2 self half)
    {
        int tiles = (N + 127) / 128;
        mma_gemm_kernel<1><<<tiles, 256, SMEM_MMA>>>(b1_l, gamma, beta, mu, var, nullptr, N);
    }

    // layer-2: A2[:, 0:256] = mean(h1 nbrs)  (fp16 packed)
    gather2_kernel<<<(N * 32 + 255) / 256, 256>>>(N);

    // out = l2norm(A2 @ B2 + b2)
    {
        int tiles = (N + 127) / 128;
        mma_gemm_kernel<2><<<tiles, 256, SMEM_MMA>>>(b2_l, nullptr, nullptr, nullptr, nullptr, out, N);
    }
}

// round 13
// speedup vs baseline: 5.1831x; 1.4543x over previous
#include <cuda_runtime.h>
#include <cuda_fp16.h>
#include <cstdint>

#define N_NODES 100000
#define E_MAX   800000
#define F_IN 128
#define F_H  256
#define BN_EPS 1e-5f
#define L2_EPS 1e-12f

// ---------------- scratch (device globals; referenced ONLY from device code) --
__device__ __align__(16) uint32_t g_h1h[(size_t)N_NODES * 128];  // h1 fp16 packed
__device__ __align__(16) uint32_t g_xh [(size_t)N_NODES * 64];   // x  fp16 packed
__device__ __align__(16) uint32_t g_A1[(size_t)N_NODES * 128];   // [agg128|self128]
__device__ __align__(16) uint32_t g_A2[(size_t)N_NODES * 256];   // [agg256|self256]
__device__ int   g_cnt[N_NODES];
__device__ int   g_cur[N_NODES];
__device__ int   g_rowptr[N_NODES + 1];
__device__ int   g_bsum[128];
__device__ int   g_esrc[E_MAX];
__device__ int   g_is64;

// weights transposed fp16: B[n][k], n = out col (256), k = in
__device__ __align__(16) __half g_B1[256 * 256];
__device__ __align__(16) __half g_B2[256 * 512];

// ---------------- helpers ----------------
__device__ __forceinline__ uint32_t pack_f16(float x, float y) {
    __half2 h = __floats2half2_rn(x, y);
    return *(uint32_t*)&h;
}

// ---------------- edge-index dtype detection ----------------
__global__ void detect_kernel(const int* __restrict__ ei_raw) {
    __shared__ int any_nonzero;
    if (threadIdx.x == 0) any_nonzero = 0;
    __syncthreads();
    int w = ei_raw[threadIdx.x * 2 + 1];
    if (w != 0) atomicOr(&any_nonzero, 1);
    __syncthreads();
    if (threadIdx.x == 0) g_is64 = any_nonzero ? 0 : 1;
}

__device__ __forceinline__ int edge_at(const void* ei, size_t i) {
    if (g_is64) return (int)((const long long*)ei)[i];
    return ((const int*)ei)[i];
}

// ---------------- zero counters ----------------
__global__ void zero_kernel() {
    int i = blockIdx.x * blockDim.x + threadIdx.x;
    if (i < N_NODES) { g_cnt[i] = 0; g_cur[i] = 0; }
}

// ---------------- weight prep + x fp16 convert ----------------
__global__ void prep_kernel(const float* __restrict__ W1_l, const float* __restrict__ W1_r,
                            const float* __restrict__ W2_l, const float* __restrict__ W2_r,
                            const float* __restrict__ x, int n_nodes) {
    int tid = blockIdx.x * blockDim.x + threadIdx.x;
    int nthr = gridDim.x * blockDim.x;
    for (int i = tid; i < 256 * 256; i += nthr) {
        int n = i >> 8, k = i & 255;
        float w = (k < 128) ? W1_l[k * 256 + n] : W1_r[(k - 128) * 256 + n];
        g_B1[i] = __float2half_rn(w);
    }
    for (int i = tid; i < 256 * 512; i += nthr) {
        int n = i >> 9, k = i & 511;
        float w = (k < 256) ? W2_l[k * 256 + n] : W2_r[(k - 256) * 256 + n];
        g_B2[i] = __float2half_rn(w);
    }
    // x -> fp16 packed: one float4 (4 cols) per thread-iter
    int totx = n_nodes * 32;
    for (int i = tid; i < totx; i += nthr) {
        int node = i >> 5, q = i & 31;
        float4 v = __ldg((const float4*)(x + (size_t)node * F_IN) + q);
        uint2 p = make_uint2(pack_f16(v.x, v.y), pack_f16(v.z, v.w));
        *((uint2*)(g_xh + (size_t)node * 64) + q) = p;
    }
}

// ---------------- degree histogram ----------------
__global__ void degree_kernel(const void* __restrict__ ei, int E) {
    int e = blockIdx.x * blockDim.x + threadIdx.x;
    if (e < E) {
        int d = edge_at(ei, (size_t)E + e);
        if (d >= 0 && d < N_NODES) atomicAdd(&g_cnt[d], 1);
    }
}

// ---------------- scan ----------------
__global__ void scan1_kernel(int n) {
    __shared__ int sh[1024];
    int i = blockIdx.x * 1024 + threadIdx.x;
    int v = (i < n) ? g_cnt[i] : 0;
    sh[threadIdx.x] = v;
    __syncthreads();
    #pragma unroll
    for (int o = 1; o < 1024; o <<= 1) {
        int add = (threadIdx.x >= o) ? sh[threadIdx.x - o] : 0;
        __syncthreads();
        sh[threadIdx.x] += add;
        __syncthreads();
    }
    if (i < n) g_rowptr[i] = sh[threadIdx.x] - v;
    if (threadIdx.x == 1023) g_bsum[blockIdx.x] = sh[1023];
}

__global__ void scan2_kernel(int nblocks) {
    if (threadIdx.x == 0) {
        int acc = 0;
        for (int b = 0; b < nblocks; b++) {
            int v = g_bsum[b];
            g_bsum[b] = acc;
            acc += v;
        }
    }
}

__global__ void scan3_kernel(int n, int E) {
    int i = blockIdx.x * 1024 + threadIdx.x;
    if (i < n) g_rowptr[i] += g_bsum[blockIdx.x];
    if (i == 0) g_rowptr[n] = E;
}

// ---------------- CSR fill ----------------
__global__ void fill_kernel(const void* __restrict__ ei, int E) {
    int e = blockIdx.x * blockDim.x + threadIdx.x;
    if (e >= E) return;
    int src = edge_at(ei, e);
    int dst = edge_at(ei, (size_t)E + e);
    if ((unsigned)src >= N_NODES || (unsigned)dst >= N_NODES) return;
    int pos = g_rowptr[dst] + atomicAdd(&g_cur[dst], 1);
    g_esrc[pos] = src;
}

// ---------------- gather layer 1: x fp16 -> A1 agg+self, unroll 4 -----------
// warp per node; lane covers 4 cols (uint2 of g_xh)
__global__ void gather1_kernel(int n_nodes) {
    int node = (blockIdx.x * blockDim.x + threadIdx.x) >> 5;
    int lane = threadIdx.x & 31;
    if (node >= n_nodes) return;
    int beg = g_rowptr[node], end = g_rowptr[node + 1];
    float inv = 1.0f / fmaxf((float)(end - beg), 1.0f);

    float a0 = 0.f, a1 = 0.f, a2 = 0.f, a3 = 0.f;
    int i = beg;
    for (; i + 3 < end; i += 4) {
        int s0 = __ldg(&g_esrc[i]);
        int s1 = __ldg(&g_esrc[i + 1]);
        int s2 = __ldg(&g_esrc[i + 2]);
        int s3 = __ldg(&g_esrc[i + 3]);
        uint2 v0 = __ldg((const uint2*)(g_xh + (size_t)s0 * 64) + lane);
        uint2 v1 = __ldg((const uint2*)(g_xh + (size_t)s1 * 64) + lane);
        uint2 v2 = __ldg((const uint2*)(g_xh + (size_t)s2 * 64) + lane);
        uint2 v3 = __ldg((const uint2*)(g_xh + (size_t)s3 * 64) + lane);
        float2 f;
        f = __half22float2(*(__half2*)&v0.x); a0 += f.x; a1 += f.y;
        f = __half22float2(*(__half2*)&v0.y); a2 += f.x; a3 += f.y;
        f = __half22float2(*(__half2*)&v1.x); a0 += f.x; a1 += f.y;
        f = __half22float2(*(__half2*)&v1.y); a2 += f.x; a3 += f.y;
        f = __half22float2(*(__half2*)&v2.x); a0 += f.x; a1 += f.y;
        f = __half22float2(*(__half2*)&v2.y); a2 += f.x; a3 += f.y;
        f = __half22float2(*(__half2*)&v3.x); a0 += f.x; a1 += f.y;
        f = __half22float2(*(__half2*)&v3.y); a2 += f.x; a3 += f.y;
    }
    for (; i < end; i++) {
        int s0 = __ldg(&g_esrc[i]);
        uint2 v0 = __ldg((const uint2*)(g_xh + (size_t)s0 * 64) + lane);
        float2 f;
        f = __half22float2(*(__half2*)&v0.x); a0 += f.x; a1 += f.y;
        f = __half22float2(*(__half2*)&v0.y); a2 += f.x; a3 += f.y;
    }
    size_t idx = (size_t)node * 128 + lane * 2;
    g_A1[idx]     = pack_f16(a0 * inv, a1 * inv);
    g_A1[idx + 1] = pack_f16(a2 * inv, a3 * inv);
    // self half: direct fp16 copy
    uint2 sv = __ldg((const uint2*)(g_xh + (size_t)node * 64) + lane);
    *((uint2*)(g_A1 + idx + 64)) = sv;
}

// ---------------- gather layer 2: h1 fp16 -> A2 agg half, unroll 4 ----------
// warp per node; lane covers 8 cols (uint4 of g_h1h)
__global__ void gather2_kernel(int n_nodes) {
    int node = (blockIdx.x * blockDim.x + threadIdx.x) >> 5;
    int lane = threadIdx.x & 31;
    if (node >= n_nodes) return;
    int beg = g_rowptr[node], end = g_rowptr[node + 1];
    float inv = 1.0f / fmaxf((float)(end - beg), 1.0f);

    float acc[8] = {0.f, 0.f, 0.f, 0.f, 0.f, 0.f, 0.f, 0.f};
    int i = beg;
    for (; i + 3 < end; i += 4) {
        int s0 = __ldg(&g_esrc[i]);
        int s1 = __ldg(&g_esrc[i + 1]);
        int s2 = __ldg(&g_esrc[i + 2]);
        int s3 = __ldg(&g_esrc[i + 3]);
        uint4 v0 = __ldg((const uint4*)(g_h1h + (size_t)s0 * 128) + lane);
        uint4 v1 = __ldg((const uint4*)(g_h1h + (size_t)s1 * 128) + lane);
        uint4 v2 = __ldg((const uint4*)(g_h1h + (size_t)s2 * 128) + lane);
        uint4 v3 = __ldg((const uint4*)(g_h1h + (size_t)s3 * 128) + lane);
        const __half2* h;
        h = (const __half2*)&v0;
        #pragma unroll
        for (int q = 0; q < 4; q++) { float2 f = __half22float2(h[q]); acc[q*2] += f.x; acc[q*2+1] += f.y; }
        h = (const __half2*)&v1;
        #pragma unroll
        for (int q = 0; q < 4; q++) { float2 f = __half22float2(h[q]); acc[q*2] += f.x; acc[q*2+1] += f.y; }
        h = (const __half2*)&v2;
        #pragma unroll
        for (int q = 0; q < 4; q++) { float2 f = __half22float2(h[q]); acc[q*2] += f.x; acc[q*2+1] += f.y; }
        h = (const __half2*)&v3;
        #pragma unroll
        for (int q = 0; q < 4; q++) { float2 f = __half22float2(h[q]); acc[q*2] += f.x; acc[q*2+1] += f.y; }
    }
    for (; i < end; i++) {
        int s0 = __ldg(&g_esrc[i]);
        uint4 v0 = __ldg((const uint4*)(g_h1h + (size_t)s0 * 128) + lane);
        const __half2* h = (const __half2*)&v0;
        #pragma unroll
        for (int q = 0; q < 4; q++) { float2 f = __half22float2(h[q]); acc[q*2] += f.x; acc[q*2+1] += f.y; }
    }
    uint32_t outw[4];
    #pragma unroll
    for (int q = 0; q < 4; q++)
        outw[q] = pack_f16(acc[q * 2] * inv, acc[q * 2 + 1] * inv);
    *((uint4*)(g_A2 + (size_t)node * 256) + lane) = *(uint4*)outw;
}

// ================= warp-level fp16 MMA GEMM, cp.async + ldmatrix =============
__device__ __forceinline__ void mma16816(float* c, const uint32_t* a, const uint32_t* b) {
    asm volatile(
        "mma.sync.aligned.m16n8k16.row.col.f32.f16.f16.f32 "
        "{%0,%1,%2,%3}, {%4,%5,%6,%7}, {%8,%9}, {%0,%1,%2,%3};"
        : "+f"(c[0]), "+f"(c[1]), "+f"(c[2]), "+f"(c[3])
        : "r"(a[0]), "r"(a[1]), "r"(a[2]), "r"(a[3]), "r"(b[0]), "r"(b[1]));
}

__device__ __forceinline__ void ldsm_x4(uint32_t* r, uint32_t addr) {
    asm volatile("ldmatrix.sync.aligned.m8n8.x4.shared.b16 {%0,%1,%2,%3}, [%4];"
        : "=r"(r[0]), "=r"(r[1]), "=r"(r[2]), "=r"(r[3]) : "r"(addr));
}
__device__ __forceinline__ void ldsm_x2(uint32_t* r, uint32_t addr) {
    asm volatile("ldmatrix.sync.aligned.m8n8.x2.shared.b16 {%0,%1}, [%2];"
        : "=r"(r[0]), "=r"(r[1]) : "r"(addr));
}

__device__ __forceinline__ void cp16(uint32_t smem_byte, const void* gmem) {
    asm volatile("cp.async.cg.shared.global [%0], [%1], 16;" :: "r"(smem_byte), "l"(gmem));
}

// stage layout (u32): A@0 (128x20), B@2560 (256x20)
#define SM_A 0
#define SM_B 2560
#define STG_U32 7680
#define SMEM_MMA (2 * STG_U32 * 4)     // 61440 B

template<int LAYER>
__global__ void __launch_bounds__(256, 1)
mma_gemm_kernel(const float* __restrict__ bias,
                const float* __restrict__ gamma, const float* __restrict__ beta,
                const float* __restrict__ mu,    const float* __restrict__ var,
                float* __restrict__ outp, int n_rows)
{
    constexpr int KTOT = (LAYER == 1) ? 256 : 512;
    constexpr int NCH  = KTOT / 32;
    constexpr int RS   = KTOT / 2;        // A row stride in u32
    const uint32_t* A = (LAYER == 1) ? g_A1 : g_A2;
    const __half* B   = (LAYER == 1) ? g_B1 : g_B2;

    extern __shared__ uint32_t smu[];
    __shared__ float s_scale[256], s_shift[256];
    __shared__ float s_ss[128];

    const int t = threadIdx.x, wid = t >> 5, lane = t & 31;
    const int grp = lane >> 2, tig = lane & 3;
    const int wm = wid & 3, wn = wid >> 2;
    const int row0 = blockIdx.x * 128;

    uint32_t smem_base;
    asm("{ .reg .u64 tt; cvta.to.shared.u64 tt, %1; cvt.u32.u64 %0, tt; }"
        : "=r"(smem_base) : "l"(smu));

    if (LAYER == 1) {
        float s = gamma[t] * rsqrtf(var[t] + BN_EPS);
        s_scale[t] = s;
        s_shift[t] = beta[t] + (bias[t] - mu[t]) * s;
    } else {
        s_scale[t] = 1.0f;
        s_shift[t] = bias[t];
    }
    if (t < 128) s_ss[t] = 0.0f;

    auto load_chunk = [&](int ch, int stg) {
        uint32_t sb = smem_base + stg * (STG_U32 * 4);
        #pragma unroll
        for (int l = 0; l < 2; l++) {
            int id = t + l * 256;
            int r = id >> 2, q = id & 3;
            int gr = row0 + r;
            if (gr >= n_rows) gr = n_rows - 1;
            size_t off = ((size_t)gr * RS + ch * 16 + q * 4) * 4;
            cp16(sb + (SM_A + r * 20 + q * 4) * 4, (const char*)A + off);
        }
        #pragma unroll
        for (int l = 0; l < 4; l++) {
            int id = t + l * 256;
            int n = id >> 2, q = id & 3;
            size_t off = ((size_t)n * KTOT + ch * 32) * 2 + q * 16;
            cp16(sb + (SM_B + n * 20 + q * 4) * 4, (const char*)B + off);
        }
        asm volatile("cp.async.commit_group;");
    };

    float acc[2][16][4];
    #pragma unroll
    for (int mt = 0; mt < 2; mt++)
        #pragma unroll
        for (int nt = 0; nt < 16; nt++)
            #pragma unroll
            for (int q = 0; q < 4; q++) acc[mt][nt][q] = 0.0f;

    const int a_row_in_tile = (lane & 7) + ((lane >> 3) & 1) * 8;
    const int a_kof4 = ((lane >> 4) & 1) * 4;
    const int b_row_in_tile = (lane & 7);
    const int b_kof4 = ((lane >> 3) & 1) * 4;

    load_chunk(0, 0);

    for (int ch = 0; ch < NCH; ch++) {
        if (ch + 1 < NCH) {
            load_chunk(ch + 1, (ch + 1) & 1);
            asm volatile("cp.async.wait_group 1;");
        } else {
            asm volatile("cp.async.wait_group 0;");
        }
        __syncthreads();

        uint32_t sb = smem_base + (ch & 1) * (STG_U32 * 4);
        #pragma unroll
        for (int s16 = 0; s16 < 2; s16++) {
            const int pb = s16 * 8;
            uint32_t ah[2][4];
            #pragma unroll
            for (int mt = 0; mt < 2; mt++) {
                int row = wm * 32 + mt * 16 + a_row_in_tile;
                ldsm_x4(ah[mt], sb + (SM_A + row * 20 + pb + a_kof4) * 4);
            }
            uint32_t baddr0 = sb + (SM_B + (wn * 128 + b_row_in_tile) * 20 + pb + b_kof4) * 4;
            #pragma unroll
            for (int nt = 0; nt < 16; nt++) {
                uint32_t bh[2];
                ldsm_x2(bh, baddr0 + nt * 8 * 20 * 4);
                mma16816(acc[0][nt], ah[0], bh);
                mma16816(acc[1][nt], ah[1], bh);
            }
        }
        __syncthreads();
    }

    if (LAYER == 1) {
        #pragma unroll
        for (int mt = 0; mt < 2; mt++) {
            int r_lo = row0 + wm * 32 + mt * 16 + grp;
            int r_hi = r_lo + 8;
            #pragma unroll
            for (int nt = 0; nt < 16; nt++) {
                int c = wn * 128 + nt * 8 + 2 * tig;
                float s0 = s_scale[c],   sh0 = s_shift[c];
                float s1 = s_scale[c+1], sh1 = s_shift[c+1];
                if (r_lo < n_rows) {
                    float v0 = fmaxf(fmaf(acc[mt][nt][0], s0, sh0), 0.f);
                    float v1 = fmaxf(fmaf(acc[mt][nt][1], s1, sh1), 0.f);
                    uint32_t pw = pack_f16(v0, v1);
                    g_h1h[(size_t)r_lo * 128 + (c >> 1)] = pw;
                    g_A2[(size_t)r_lo * 256 + 128 + (c >> 1)] = pw;
                }
                if (r_hi < n_rows) {
                    float v2 = fmaxf(fmaf(acc[mt][nt][2], s0, sh0), 0.f);
                    float v3 = fmaxf(fmaf(acc[mt][nt][3], s1, sh1), 0.f);
                    uint32_t pw = pack_f16(v2, v3);
                    g_h1h[(size_t)r_hi * 128 + (c >> 1)] = pw;
                    g_A2[(size_t)r_hi * 256 + 128 + (c >> 1)] = pw;
                }
            }
        }
    } else {
        float ssl[2] = {0.f, 0.f}, ssh[2] = {0.f, 0.f};
        #pragma unroll
        for (int mt = 0; mt < 2; mt++) {
            #pragma unroll
            for (int nt = 0; nt < 16; nt++) {
                int c = wn * 128 + nt * 8 + 2 * tig;
                float v0 = acc[mt][nt][0] + s_shift[c];
                float v1 = acc[mt][nt][1] + s_shift[c + 1];
                float v2 = acc[mt][nt][2] + s_shift[c];
                float v3 = acc[mt][nt][3] + s_shift[c + 1];
                ssl[mt] += v0 * v0 + v1 * v1;
                ssh[mt] += v2 * v2 + v3 * v3;
            }
        }
        #pragma unroll
        for (int mt = 0; mt < 2; mt++) {
            #pragma unroll
            for (int o = 1; o < 4; o <<= 1) {
                ssl[mt] += __shfl_xor_sync(0xFFFFFFFFu, ssl[mt], o);
                ssh[mt] += __shfl_xor_sync(0xFFFFFFFFu, ssh[mt], o);
            }
        }
        if (tig == 0) {
            #pragma unroll
            for (int mt = 0; mt < 2; mt++) {
                atomicAdd(&s_ss[wm * 32 + mt * 16 + grp], ssl[mt]);
                atomicAdd(&s_ss[wm * 32 + mt * 16 + grp + 8], ssh[mt]);
            }
        }
        __syncthreads();
        #pragma unroll
        for (int mt = 0; mt < 2; mt++) {
            int lr = wm * 32 + mt * 16 + grp;
            int r_lo = row0 + lr, r_hi = r_lo + 8;
            float invlo = 1.0f / fmaxf(sqrtf(s_ss[lr]), L2_EPS);
            float invhi = 1.0f / fmaxf(sqrtf(s_ss[lr + 8]), L2_EPS);
            #pragma unroll
            for (int nt = 0; nt < 16; nt++) {
                int c = wn * 128 + nt * 8 + 2 * tig;
                if (r_lo < n_rows) {
                    float v0 = (acc[mt][nt][0] + s_shift[c]) * invlo;
                    float v1 = (acc[mt][nt][1] + s_shift[c + 1]) * invlo;
                    *(float2*)(outp + (size_t)r_lo * 256 + c) = make_float2(v0, v1);
                }
                if (r_hi < n_rows) {
                    float v2 = (acc[mt][nt][2] + s_shift[c]) * invhi;
                    float v3 = (acc[mt][nt][3] + s_shift[c + 1]) * invhi;
                    *(float2*)(outp + (size_t)r_hi * 256 + c) = make_float2(v2, v3);
                }
            }
        }
    }
}

// ---------------- launch ----------------
extern "C" void kernel_launch(void* const* d_in, const int* in_sizes, int n_in,
                              void* d_out, int out_size) {
    const float* x      = (const float*)d_in[0];
    const void*  ei     = d_in[1];
    const float* W1_l   = (const float*)d_in[2];
    const float* b1_l   = (const float*)d_in[3];
    const float* W1_r   = (const float*)d_in[4];
    const float* gamma  = (const float*)d_in[5];
    const float* beta   = (const float*)d_in[6];
    const float* mu     = (const float*)d_in[7];
    const float* var    = (const float*)d_in[8];
    const float* W2_l   = (const float*)d_in[9];
    const float* b2_l   = (const float*)d_in[10];
    const float* W2_r   = (const float*)d_in[11];
    float* out = (float*)d_out;

    const int N = in_sizes[0] / F_IN;     // 100000
    const int E = in_sizes[1] / 2;        // 800000
    const int nsb = (N + 1023) / 1024;

    cudaFuncSetAttribute(mma_gemm_kernel<1>, cudaFuncAttributeMaxDynamicSharedMemorySize, SMEM_MMA);
    cudaFuncSetAttribute(mma_gemm_kernel<2>, cudaFuncAttributeMaxDynamicSharedMemorySize, SMEM_MMA);

    detect_kernel<<<1, 128>>>((const int*)ei);
    zero_kernel<<<(N + 255) / 256, 256>>>();
    prep_kernel<<<512, 256>>>(W1_l, W1_r, W2_l, W2_r, x, N);

    // CSR build
    degree_kernel<<<(E + 255) / 256, 256>>>(ei, E);
    scan1_kernel<<<nsb, 1024>>>(N);
    scan2_kernel<<<1, 32>>>(nsb);
    scan3_kernel<<<nsb, 1024>>>(N, E);
    fill_kernel<<<(E + 255) / 256, 256>>>(ei, E);

    // layer-1: A1 = [mean(x nbrs) | x]  (fp16)
    gather1_kernel<<<(N * 32 + 255) / 256, 256>>>(N);

    // h1 = relu(BN(A1 @ B1)) -> g_h1h fp16 (+ A2 self half)
    {
        int tiles = (N + 127) / 128;
        mma_gemm_kernel<1><<<tiles, 256, SMEM_MMA>>>(b1_l, gamma, beta, mu, var, nullptr, N);
    }

    // layer-2: A2[:, 0:256] = mean(h1 nbrs)
    gather2_kernel<<<(N * 32 + 255) / 256, 256>>>(N);

    // out = l2norm(A2 @ B2 + b2)
    {
        int tiles = (N + 127) / 128;
        mma_gemm_kernel<2><<<tiles, 256, SMEM_MMA>>>(b2_l, nullptr, nullptr, nullptr, nullptr, out, N);
    }
}